// round 1
// baseline (speedup 1.0000x reference)
#include <cuda_runtime.h>
#include <cuda_bf16.h>
#include <math.h>

// Problem constants
#define BB 4
#define QQ 16384
#define SS 4
#define HD 256
#define HH 128
#define WW 128
#define HWSZ (HH*WW)          // 16384
#define MTOT (BB*QQ)          // 65536
#define OFFSET_SCALE 0.05f

// ---------------- scratch (device globals; no runtime alloc allowed) ----------
__device__ float g_pf [(size_t)BB*HWSZ*HD];   // pf in HWC layout  [b][hw][d]  67MB
__device__ float g_pq [(size_t)MTOT*HD];      // masked pq         67MB
__device__ float g_ctx[(size_t)MTOT*HD];      // masked ctx        67MB
__device__ float g_h1 [(size_t)MTOT*HD];      // relu(hcat@W1+b1)  67MB
__device__ float g_samp[(size_t)MTOT*12];     // per query: 4x (gx,gy,w)

// ---------------- tiled fp32 GEMM: C[M,N] = A[M,K] @ W[K,N] + bias -----------
// MODE 0: A(m,k) = A0[m*K + k]                       (row-major)
// MODE 1: A(m,k) = A0[((m>>14)*256 + k)*16384 + (m&16383)]   (feature_map CHW)
// MODE 2: A(m,k) = k<256 ? A0[m*256+k] : A1[m*256+k-256]     (hcat = [pq|ctx])
template<int MODE>
__global__ void __launch_bounds__(256)
gemm_k(const float* __restrict__ A0, const float* __restrict__ A1,
       const float* __restrict__ Wm, const float* __restrict__ Bias,
       float* __restrict__ C, int M, int N, int K,
       int doRelu, const int* __restrict__ mask)
{
    __shared__ float As[16*68];   // k-major, padded stride 68 (float4-aligned)
    __shared__ float Bs[16*64];

    const int t  = threadIdx.x;
    const int m0 = blockIdx.y * 64;
    const int n0 = blockIdx.x * 64;
    const int ty = t >> 4;        // 0..15 -> output rows ty*4..+3
    const int tx = t & 15;        // 0..15 -> output cols tx*4..+3

    float acc[4][4];
#pragma unroll
    for (int i=0;i<4;i++)
#pragma unroll
        for (int j=0;j<4;j++) acc[i][j]=0.f;

    for (int k0 = 0; k0 < K; k0 += 16) {
        // ---- load A tile into As[k][m] ----
        if (MODE == 1) {
            const int kRow = t >> 4;           // 0..15
            const int m4   = (t & 15) * 4;     // 0..60
            const float* src = A0 + ((size_t)(m0 >> 14) * 256 + (k0 + kRow)) * (size_t)HWSZ
                                  + (m0 & (HWSZ-1)) + m4;
            float4 v = *(const float4*)src;
            *(float4*)&As[kRow*68 + m4] = v;
        } else {
            const int row = t >> 2;            // 0..63
            const int kk  = (t & 3) * 4;       // 0..12
            const int m   = m0 + row;
            float4 v;
            if (MODE == 2) {
                const int k = k0 + kk;         // group of 4 never straddles 256
                const float* src = (k < 256) ? (A0 + (size_t)m*256 + k)
                                             : (A1 + (size_t)m*256 + (k-256));
                v = *(const float4*)src;
            } else {
                v = *(const float4*)(A0 + (size_t)m*K + k0 + kk);
            }
            As[(kk+0)*68+row]=v.x; As[(kk+1)*68+row]=v.y;
            As[(kk+2)*68+row]=v.z; As[(kk+3)*68+row]=v.w;
        }
        // ---- load W tile into Bs[k][n] ----
        {
            const int kr = t >> 4;             // 0..15
            const int nn = (t & 15) * 4;       // 0..60
            float4 v = *(const float4*)(Wm + (size_t)(k0+kr)*N + n0 + nn);
            *(float4*)&Bs[kr*64 + nn] = v;
        }
        __syncthreads();

#pragma unroll
        for (int k = 0; k < 16; k++) {
            float a[4], b[4];
#pragma unroll
            for (int i=0;i<4;i++) a[i] = As[k*68 + ty*4 + i];
#pragma unroll
            for (int j=0;j<4;j++) b[j] = Bs[k*64 + tx*4 + j];
#pragma unroll
            for (int i=0;i<4;i++)
#pragma unroll
                for (int j=0;j<4;j++) acc[i][j] = fmaf(a[i], b[j], acc[i][j]);
        }
        __syncthreads();
    }

    // ---- epilogue ----
#pragma unroll
    for (int i=0;i<4;i++) {
        const int m = m0 + ty*4 + i;
        const float msc = mask ? (mask[m] ? 1.f : 0.f) : 1.f;
#pragma unroll
        for (int j=0;j<4;j++) {
            const int n = n0 + tx*4 + j;
            float v = acc[i][j] + Bias[n];
            if (doRelu) v = fmaxf(v, 0.f);
            C[(size_t)m*N + n] = v * msc;
        }
    }
}

// ------------- offsets + softmax weights: one warp per query -----------------
__global__ void __launch_bounds__(256)
offw_kernel(const float* __restrict__ q,
            const float* __restrict__ Wo, const float* __restrict__ bo,
            const float* __restrict__ Ww, const float* __restrict__ bw,
            const float* __restrict__ ref, float* __restrict__ samp)
{
    const int warp = (blockIdx.x * blockDim.x + threadIdx.x) >> 5;
    const int lane = threadIdx.x & 31;
    if (warp >= MTOT) return;

    const float* qr = q + (size_t)warp * 256;
    float ao[8] = {0,0,0,0,0,0,0,0};
    float aw[4] = {0,0,0,0};
#pragma unroll
    for (int kk = 0; kk < 8; kk++) {
        const int k = kk*32 + lane;
        const float qv = qr[k];
#pragma unroll
        for (int j=0;j<8;j++) ao[j] = fmaf(qv, Wo[k*8+j], ao[j]);
#pragma unroll
        for (int j=0;j<4;j++) aw[j] = fmaf(qv, Ww[k*4+j], aw[j]);
    }
#pragma unroll
    for (int j=0;j<8;j++)
#pragma unroll
        for (int o=16;o;o>>=1) ao[j] += __shfl_xor_sync(0xffffffffu, ao[j], o);
#pragma unroll
    for (int j=0;j<4;j++)
#pragma unroll
        for (int o=16;o;o>>=1) aw[j] += __shfl_xor_sync(0xffffffffu, aw[j], o);

    if (lane == 0) {
        const float rx = ref[(size_t)warp*2+0];
        const float ry = ref[(size_t)warp*2+1];
        // softmax over 4
        float v[4], mx = -1e30f;
#pragma unroll
        for (int j=0;j<4;j++) { v[j] = aw[j] + bw[j]; mx = fmaxf(mx, v[j]); }
        float s = 0.f;
#pragma unroll
        for (int j=0;j<4;j++) { v[j] = __expf(v[j]-mx); s += v[j]; }
        const float inv = 1.f / s;
        float* o = samp + (size_t)warp*12;
#pragma unroll
        for (int sI=0; sI<4; sI++) {
            float ox = tanhf(ao[2*sI+0] + bo[2*sI+0]) * OFFSET_SCALE;
            float oy = tanhf(ao[2*sI+1] + bo[2*sI+1]) * OFFSET_SCALE;
            float gx = fminf(fmaxf(rx + ox, -1.2f), 1.2f);
            float gy = fminf(fmaxf(ry + oy, -1.2f), 1.2f);
            o[sI*3+0] = gx;
            o[sI*3+1] = gy;
            o[sI*3+2] = v[sI]*inv;
        }
    }
}

// ------------- bilinear gather + weighted ctx: one block (256 thr) per query -
__global__ void __launch_bounds__(256)
sample_kernel(const float* __restrict__ pf, const float* __restrict__ samp,
              const int* __restrict__ mask, float* __restrict__ ctx)
{
    const int r = blockIdx.x;
    const int d = threadIdx.x;
    if (!mask[r]) { ctx[(size_t)r*256 + d] = 0.f; return; }

    __shared__ float sp[12];
    if (d < 12) sp[d] = samp[(size_t)r*12 + d];
    __syncthreads();

    const int b = r >> 14;
    const float* base = pf + (size_t)b * HWSZ * 256;
    float acc = 0.f;
#pragma unroll
    for (int s = 0; s < 4; s++) {
        const float gx = sp[s*3+0], gy = sp[s*3+1], w = sp[s*3+2];
        const float x = (gx + 1.f) * 0.5f * (WW - 1);
        const float y = (gy + 1.f) * 0.5f * (HH - 1);
        const float x0f = floorf(x), y0f = floorf(y);
        const int x0 = (int)x0f, y0 = (int)y0f;
        const float wx1 = x - x0f, wy1 = y - y0f;
        const float wx0 = 1.f - wx1, wy0 = 1.f - wy1;

        const int xs[2] = {x0, x0+1};
        const int ys[2] = {y0, y0+1};
        const float wxs[2] = {wx0, wx1};
        const float wys[2] = {wy0, wy1};
#pragma unroll
        for (int cy=0; cy<2; cy++)
#pragma unroll
            for (int cx=0; cx<2; cx++) {
                const int xi = xs[cx], yi = ys[cy];
                if (xi >= 0 && xi < WW && yi >= 0 && yi < HH) {
                    const float cw = w * wxs[cx] * wys[cy];
                    acc = fmaf(cw, base[(((size_t)yi*WW + xi) << 8) + d], acc);
                }
            }
    }
    ctx[(size_t)r*256 + d] = acc;
}

// -----------------------------------------------------------------------------
extern "C" void kernel_launch(void* const* d_in, const int* in_sizes, int n_in,
                              void* d_out, int out_size)
{
    const float* queries  = (const float*)d_in[0];
    const float* ref_pts  = (const float*)d_in[1];
    const float* fmap     = (const float*)d_in[2];
    const int*   vmask    = (const int*)  d_in[3];   // bool materialized as int32 (assumption)
    const float* Wq = (const float*)d_in[4];
    const float* bq = (const float*)d_in[5];
    const float* Wf = (const float*)d_in[6];
    const float* bf = (const float*)d_in[7];
    const float* Wo = (const float*)d_in[8];
    const float* bo = (const float*)d_in[9];
    const float* Ww = (const float*)d_in[10];
    const float* bw = (const float*)d_in[11];
    const float* W1 = (const float*)d_in[12];
    const float* b1 = (const float*)d_in[13];
    const float* W2 = (const float*)d_in[14];
    const float* b2 = (const float*)d_in[15];
    float* out = (float*)d_out;

    float *pf, *pq, *ctx, *h1, *samp;
    cudaGetSymbolAddress((void**)&pf,   g_pf);
    cudaGetSymbolAddress((void**)&pq,   g_pq);
    cudaGetSymbolAddress((void**)&ctx,  g_ctx);
    cudaGetSymbolAddress((void**)&h1,   g_h1);
    cudaGetSymbolAddress((void**)&samp, g_samp);

    const dim3 g256(256/64, MTOT/64);   // N=256 tiles x M tiles

    // 1) pf (HWC) = conv1x1(feature_map, Wf) + bf
    gemm_k<1><<<g256, 256>>>(fmap, nullptr, Wf, bf, pf, MTOT, 256, 256, 0, nullptr);
    // 2) pq = (queries @ Wq + bq) * mask
    gemm_k<0><<<g256, 256>>>(queries, nullptr, Wq, bq, pq, MTOT, 256, 256, 0, vmask);
    // 3) offsets + softmax weights per query
    offw_kernel<<<MTOT/8, 256>>>(queries, Wo, bo, Ww, bw, ref_pts, samp);
    // 4) bilinear sample + weighted sum -> ctx (masked)
    sample_kernel<<<MTOT, 256>>>(pf, samp, vmask, ctx);
    // 5) h1 = relu([pq|ctx] @ W1 + b1)
    gemm_k<2><<<g256, 256>>>(pq, ctx, W1, b1, h1, MTOT, 256, 512, 1, nullptr);
    // 6) out = h1 @ W2 + b2
    gemm_k<0><<<g256, 256>>>(h1, nullptr, W2, b2, out, MTOT, 256, 256, 0, nullptr);
}

// round 2
// speedup vs baseline: 1.9336x; 1.9336x over previous
#include <cuda_runtime.h>
#include <cuda_bf16.h>
#include <math.h>

// Problem constants
#define BB 4
#define QQ 16384
#define SS 4
#define HD 256
#define HH 128
#define WW 128
#define HWSZ (HH*WW)          // 16384
#define MTOT (BB*QQ)          // 65536
#define OFFSET_SCALE 0.05f

// ---------------- scratch (device globals; no runtime alloc allowed) ----------
__device__ float g_fmT[(size_t)BB*HWSZ*HD];   // feature map HWC    67MB
__device__ float g_pf [(size_t)BB*HWSZ*HD];   // pf in HWC layout   67MB
__device__ float g_pq [(size_t)MTOT*HD];      // masked pq          67MB
__device__ float g_ctx[(size_t)MTOT*HD];      // masked ctx         67MB
__device__ float g_h1 [(size_t)MTOT*HD];      // relu(hcat@W1+b1)   67MB
__device__ float g_samp[(size_t)MTOT*12];     // per query: 4x (gx,gy,w)

// ---------------- helpers ----------------------------------------------------
__device__ __forceinline__ unsigned tf32cvt(float f) {
    unsigned u;
    asm("cvt.rna.tf32.f32 %0, %1;" : "=r"(u) : "f"(f));
    return u;
}

__device__ __forceinline__ void mma8(float* c,
                                     unsigned a0, unsigned a1, unsigned a2, unsigned a3,
                                     unsigned b0, unsigned b1) {
    asm volatile(
        "mma.sync.aligned.m16n8k8.row.col.f32.tf32.tf32.f32 "
        "{%0,%1,%2,%3},{%4,%5,%6,%7},{%8,%9},{%0,%1,%2,%3};"
        : "+f"(c[0]), "+f"(c[1]), "+f"(c[2]), "+f"(c[3])
        : "r"(a0), "r"(a1), "r"(a2), "r"(a3), "r"(b0), "r"(b1));
}

// ---------------- CHW -> HWC transpose ---------------------------------------
__global__ void __launch_bounds__(256)
transpose_k(const float* __restrict__ fm, float* __restrict__ fmT)
{
    __shared__ float ts[32][33];
    const int b  = blockIdx.z;
    const int c0 = blockIdx.y * 32;
    const int h0 = blockIdx.x * 32;
    const int t  = threadIdx.x;

    {
        const int cl = t >> 3, h4 = (t & 7) * 4;
        float4 v = *(const float4*)(fm + ((size_t)(b*256 + c0 + cl)) * HWSZ + h0 + h4);
        ts[h4+0][cl] = v.x; ts[h4+1][cl] = v.y; ts[h4+2][cl] = v.z; ts[h4+3][cl] = v.w;
    }
    __syncthreads();
    {
        const int hl = t >> 3, c4 = (t & 7) * 4;
        float4 o = make_float4(ts[hl][c4], ts[hl][c4+1], ts[hl][c4+2], ts[hl][c4+3]);
        *(float4*)(fmT + ((size_t)((b << 14) + h0 + hl)) * 256 + c0 + c4) = o;
    }
}

// ---------------- TF32 tensor-core GEMM --------------------------------------
// C[M,N] = A[M,K] @ W[K,N] + bias, optional relu, optional row mask.
// BM=128, BN=64, BK=32; 256 threads = 8 warps (4 m x 2 n); warp tile 32x32.
// MODE 0: A(m,k) = A0[m*K+k]
// MODE 2: A(m,k) = k<256 ? A0[m*256+k] : A1[m*256+k-256]
#define LDA 36
#define LDB 68
template<int MODE>
__global__ void __launch_bounds__(256)
gemm_tc(const float* __restrict__ A0, const float* __restrict__ A1,
        const float* __restrict__ Wm, const float* __restrict__ Bias,
        float* __restrict__ C, int M, int N, int K,
        int doRelu, const int* __restrict__ mask)
{
    __shared__ unsigned As[128 * LDA];   // m-major, tf32 bits
    __shared__ unsigned Bs[32 * LDB];    // k-major, tf32 bits

    const int t    = threadIdx.x;
    const int m0   = blockIdx.y * 128;
    const int n0   = blockIdx.x * 64;
    const int wid  = t >> 5;
    const int lane = t & 31;
    const int wm   = wid >> 1;          // 0..3
    const int wn   = wid & 1;           // 0..1
    const int g    = lane >> 2;         // 0..7
    const int tig  = lane & 3;          // 0..3

    float acc[2][4][4];
#pragma unroll
    for (int i=0;i<2;i++)
#pragma unroll
        for (int j=0;j<4;j++)
#pragma unroll
            for (int l=0;l<4;l++) acc[i][j][l] = 0.f;

    for (int k0 = 0; k0 < K; k0 += 32) {
        // ---- A tile 128x32 ----
#pragma unroll
        for (int i = 0; i < 4; i++) {
            const int idx = t + i * 256;        // 0..1023
            const int row = idx >> 3;
            const int k4  = (idx & 7) * 4;
            const int m   = m0 + row;
            const int kg  = k0 + k4;
            const float* src;
            if (MODE == 2) src = (kg < 256) ? (A0 + (size_t)m*256 + kg)
                                            : (A1 + (size_t)m*256 + (kg-256));
            else           src = A0 + (size_t)m*K + kg;
            float4 v = *(const float4*)src;
            uint4 u = make_uint4(tf32cvt(v.x), tf32cvt(v.y), tf32cvt(v.z), tf32cvt(v.w));
            *(uint4*)&As[row*LDA + k4] = u;
        }
        // ---- B tile 32x64 ----
#pragma unroll
        for (int i = 0; i < 2; i++) {
            const int idx  = t + i * 256;       // 0..511
            const int krow = idx >> 4;
            const int n4   = (idx & 15) * 4;
            float4 v = *(const float4*)(Wm + (size_t)(k0+krow)*N + n0 + n4);
            uint4 u = make_uint4(tf32cvt(v.x), tf32cvt(v.y), tf32cvt(v.z), tf32cvt(v.w));
            *(uint4*)&Bs[krow*LDB + n4] = u;
        }
        __syncthreads();

#pragma unroll
        for (int ks = 0; ks < 4; ks++) {
            const int kk = ks * 8;
            unsigned a[2][4], b[4][2];
#pragma unroll
            for (int mt = 0; mt < 2; mt++) {
                const int rm = wm*32 + mt*16;
                a[mt][0] = As[(rm +     g)*LDA + kk + tig];
                a[mt][1] = As[(rm + 8 + g)*LDA + kk + tig];
                a[mt][2] = As[(rm +     g)*LDA + kk + tig + 4];
                a[mt][3] = As[(rm + 8 + g)*LDA + kk + tig + 4];
            }
#pragma unroll
            for (int nt = 0; nt < 4; nt++) {
                const int cn = wn*32 + nt*8 + g;
                b[nt][0] = Bs[(kk + tig    )*LDB + cn];
                b[nt][1] = Bs[(kk + tig + 4)*LDB + cn];
            }
#pragma unroll
            for (int mt = 0; mt < 2; mt++)
#pragma unroll
                for (int nt = 0; nt < 4; nt++)
                    mma8(acc[mt][nt], a[mt][0], a[mt][1], a[mt][2], a[mt][3],
                         b[nt][0], b[nt][1]);
        }
        __syncthreads();
    }

    // ---- epilogue ----
#pragma unroll
    for (int mt = 0; mt < 2; mt++) {
        const int r0 = m0 + wm*32 + mt*16 + g;
        const int r1 = r0 + 8;
        const float msk0 = mask ? (mask[r0] ? 1.f : 0.f) : 1.f;
        const float msk1 = mask ? (mask[r1] ? 1.f : 0.f) : 1.f;
#pragma unroll
        for (int nt = 0; nt < 4; nt++) {
            const int c0 = n0 + wn*32 + nt*8 + tig*2;
            const float b0 = Bias[c0], b1 = Bias[c0+1];
            float v00 = acc[mt][nt][0] + b0, v01 = acc[mt][nt][1] + b1;
            float v10 = acc[mt][nt][2] + b0, v11 = acc[mt][nt][3] + b1;
            if (doRelu) {
                v00 = fmaxf(v00, 0.f); v01 = fmaxf(v01, 0.f);
                v10 = fmaxf(v10, 0.f); v11 = fmaxf(v11, 0.f);
            }
            *(float2*)(C + (size_t)r0*N + c0) = make_float2(v00*msk0, v01*msk0);
            *(float2*)(C + (size_t)r1*N + c0) = make_float2(v10*msk1, v11*msk1);
        }
    }
}

// ------------- offsets + softmax weights: one warp per query -----------------
__global__ void __launch_bounds__(256)
offw_kernel(const float* __restrict__ q,
            const float* __restrict__ Wo, const float* __restrict__ bo,
            const float* __restrict__ Ww, const float* __restrict__ bw,
            const float* __restrict__ ref, float* __restrict__ samp)
{
    const int warp = (blockIdx.x * blockDim.x + threadIdx.x) >> 5;
    const int lane = threadIdx.x & 31;
    if (warp >= MTOT) return;

    const float* qr = q + (size_t)warp * 256;
    float ao[8] = {0,0,0,0,0,0,0,0};
    float aw[4] = {0,0,0,0};
#pragma unroll
    for (int kk = 0; kk < 8; kk++) {
        const int k = kk*32 + lane;
        const float qv = qr[k];
#pragma unroll
        for (int j=0;j<8;j++) ao[j] = fmaf(qv, Wo[k*8+j], ao[j]);
#pragma unroll
        for (int j=0;j<4;j++) aw[j] = fmaf(qv, Ww[k*4+j], aw[j]);
    }
#pragma unroll
    for (int j=0;j<8;j++)
#pragma unroll
        for (int o=16;o;o>>=1) ao[j] += __shfl_xor_sync(0xffffffffu, ao[j], o);
#pragma unroll
    for (int j=0;j<4;j++)
#pragma unroll
        for (int o=16;o;o>>=1) aw[j] += __shfl_xor_sync(0xffffffffu, aw[j], o);

    if (lane == 0) {
        const float rx = ref[(size_t)warp*2+0];
        const float ry = ref[(size_t)warp*2+1];
        float v[4], mx = -1e30f;
#pragma unroll
        for (int j=0;j<4;j++) { v[j] = aw[j] + bw[j]; mx = fmaxf(mx, v[j]); }
        float s = 0.f;
#pragma unroll
        for (int j=0;j<4;j++) { v[j] = __expf(v[j]-mx); s += v[j]; }
        const float inv = 1.f / s;
        float* o = samp + (size_t)warp*12;
#pragma unroll
        for (int sI=0; sI<4; sI++) {
            float ox = tanhf(ao[2*sI+0] + bo[2*sI+0]) * OFFSET_SCALE;
            float oy = tanhf(ao[2*sI+1] + bo[2*sI+1]) * OFFSET_SCALE;
            float gx = fminf(fmaxf(rx + ox, -1.2f), 1.2f);
            float gy = fminf(fmaxf(ry + oy, -1.2f), 1.2f);
            o[sI*3+0] = gx;
            o[sI*3+1] = gy;
            o[sI*3+2] = v[sI]*inv;
        }
    }
}

// ------------- bilinear gather + weighted ctx: 4 queries per block, float4 ---
__global__ void __launch_bounds__(256)
sample2_kernel(const float* __restrict__ pf, const float* __restrict__ samp,
               const int* __restrict__ mask, float* __restrict__ ctx)
{
    __shared__ float sp[48];
    const int t = threadIdx.x;
    if (t < 48) sp[t] = samp[(size_t)blockIdx.x*48 + t];
    __syncthreads();

    const int qi = t >> 6;                 // 0..3
    const int q  = blockIdx.x*4 + qi;
    const int d4 = (t & 63) * 4;

    float4 acc = make_float4(0.f, 0.f, 0.f, 0.f);
    if (mask[q]) {
        const float* base = pf + (((size_t)(q >> 14)) << 14) * 256;
#pragma unroll
        for (int s = 0; s < 4; s++) {
            const float gx = sp[qi*12 + s*3 + 0];
            const float gy = sp[qi*12 + s*3 + 1];
            const float w  = sp[qi*12 + s*3 + 2];
            const float x = (gx + 1.f) * 0.5f * (WW - 1);
            const float y = (gy + 1.f) * 0.5f * (HH - 1);
            const float x0f = floorf(x), y0f = floorf(y);
            const int x0 = (int)x0f, y0 = (int)y0f;
            const float wx1 = x - x0f, wy1 = y - y0f;
            const float wx0 = 1.f - wx1, wy0 = 1.f - wy1;
            const int   xs[2]  = {x0, x0+1};
            const int   ys[2]  = {y0, y0+1};
            const float wxs[2] = {wx0, wx1};
            const float wys[2] = {wy0, wy1};
#pragma unroll
            for (int cy=0; cy<2; cy++)
#pragma unroll
                for (int cx=0; cx<2; cx++) {
                    const int xi = xs[cx], yi = ys[cy];
                    if (xi >= 0 && xi < WW && yi >= 0 && yi < HH) {
                        const float cw = w * wxs[cx] * wys[cy];
                        float4 v = *(const float4*)(base + (((size_t)(yi*WW + xi)) << 8) + d4);
                        acc.x = fmaf(cw, v.x, acc.x);
                        acc.y = fmaf(cw, v.y, acc.y);
                        acc.z = fmaf(cw, v.z, acc.z);
                        acc.w = fmaf(cw, v.w, acc.w);
                    }
                }
        }
    }
    *(float4*)(ctx + (size_t)q*256 + d4) = acc;
}

// -----------------------------------------------------------------------------
extern "C" void kernel_launch(void* const* d_in, const int* in_sizes, int n_in,
                              void* d_out, int out_size)
{
    const float* queries  = (const float*)d_in[0];
    const float* ref_pts  = (const float*)d_in[1];
    const float* fmap     = (const float*)d_in[2];
    const int*   vmask    = (const int*)  d_in[3];
    const float* Wq = (const float*)d_in[4];
    const float* bq = (const float*)d_in[5];
    const float* Wf = (const float*)d_in[6];
    const float* bf = (const float*)d_in[7];
    const float* Wo = (const float*)d_in[8];
    const float* bo = (const float*)d_in[9];
    const float* Ww = (const float*)d_in[10];
    const float* bw = (const float*)d_in[11];
    const float* W1 = (const float*)d_in[12];
    const float* b1 = (const float*)d_in[13];
    const float* W2 = (const float*)d_in[14];
    const float* b2 = (const float*)d_in[15];
    float* out = (float*)d_out;

    float *fmT, *pf, *pq, *ctx, *h1, *samp;
    cudaGetSymbolAddress((void**)&fmT,  g_fmT);
    cudaGetSymbolAddress((void**)&pf,   g_pf);
    cudaGetSymbolAddress((void**)&pq,   g_pq);
    cudaGetSymbolAddress((void**)&ctx,  g_ctx);
    cudaGetSymbolAddress((void**)&h1,   g_h1);
    cudaGetSymbolAddress((void**)&samp, g_samp);

    const dim3 gGemm(256/64, MTOT/128);     // (4, 512)
    const dim3 gTr(HWSZ/32, 256/32, BB);    // (512, 8, 4)

    // 0) fmap CHW -> HWC
    transpose_k<<<gTr, 256>>>(fmap, fmT);
    // 1) pf = conv1x1(fmT, Wf) + bf   (HWC layout)
    gemm_tc<0><<<gGemm, 256>>>(fmT, nullptr, Wf, bf, pf, MTOT, 256, 256, 0, nullptr);
    // 2) pq = (queries @ Wq + bq) * mask
    gemm_tc<0><<<gGemm, 256>>>(queries, nullptr, Wq, bq, pq, MTOT, 256, 256, 0, vmask);
    // 3) offsets + softmax weights per query
    offw_kernel<<<MTOT/8, 256>>>(queries, Wo, bo, Ww, bw, ref_pts, samp);
    // 4) bilinear sample + weighted sum -> ctx (masked)
    sample2_kernel<<<MTOT/4, 256>>>(pf, samp, vmask, ctx);
    // 5) h1 = relu([pq|ctx] @ W1 + b1)
    gemm_tc<2><<<gGemm, 256>>>(pq, ctx, W1, b1, h1, MTOT, 256, 512, 1, nullptr);
    // 6) out = h1 @ W2 + b2
    gemm_tc<0><<<gGemm, 256>>>(h1, nullptr, W2, b2, out, MTOT, 256, 256, 0, nullptr);
}

// round 4
// speedup vs baseline: 4.1819x; 2.1628x over previous
#include <cuda_runtime.h>
#include <cuda_fp16.h>
#include <cuda_bf16.h>
#include <math.h>

// Problem constants
#define BB 4
#define QQ 16384
#define SS 4
#define HD 256
#define HH 128
#define WW 128
#define HWSZ (HH*WW)          // 16384
#define MTOT (BB*QQ)          // 65536
#define OFFSET_SCALE 0.05f

// ---------------- scratch (device globals; no runtime alloc allowed) ----------
__device__ float g_fmT[(size_t)BB*HWSZ*HD];   // feature map HWC    67MB
__device__ float g_pf [(size_t)BB*HWSZ*HD];   // pf in HWC layout   67MB
__device__ float g_pq [(size_t)MTOT*HD];      // masked pq          67MB
__device__ float g_ctx[(size_t)MTOT*HD];      // masked ctx         67MB
__device__ float g_h1 [(size_t)MTOT*HD];      // relu(hcat@W1+b1)   67MB
__device__ float g_samp[(size_t)MTOT*12];     // per query: 4x (gx,gy,w)

// ---------------- mma / ldmatrix helpers -------------------------------------
__device__ __forceinline__ void hmma16(float* c,
                                       unsigned a0, unsigned a1, unsigned a2, unsigned a3,
                                       unsigned b0, unsigned b1) {
    asm volatile(
        "mma.sync.aligned.m16n8k16.row.col.f32.f16.f16.f32 "
        "{%0,%1,%2,%3},{%4,%5,%6,%7},{%8,%9},{%0,%1,%2,%3};"
        : "+f"(c[0]), "+f"(c[1]), "+f"(c[2]), "+f"(c[3])
        : "r"(a0), "r"(a1), "r"(a2), "r"(a3), "r"(b0), "r"(b1));
}

__device__ __forceinline__ void ldsm4(unsigned& r0, unsigned& r1, unsigned& r2, unsigned& r3,
                                      unsigned addr) {
    asm volatile("ldmatrix.sync.aligned.m8n8.x4.shared.b16 {%0,%1,%2,%3}, [%4];"
                 : "=r"(r0), "=r"(r1), "=r"(r2), "=r"(r3) : "r"(addr));
}
__device__ __forceinline__ void ldsm4t(unsigned& r0, unsigned& r1, unsigned& r2, unsigned& r3,
                                       unsigned addr) {
    asm volatile("ldmatrix.sync.aligned.m8n8.x4.trans.shared.b16 {%0,%1,%2,%3}, [%4];"
                 : "=r"(r0), "=r"(r1), "=r"(r2), "=r"(r3) : "r"(addr));
}

// ---------------- CHW -> HWC transpose ---------------------------------------
__global__ void __launch_bounds__(256)
transpose_k(const float* __restrict__ fm, float* __restrict__ fmT)
{
    __shared__ float ts[32][33];
    const int b  = blockIdx.z;
    const int c0 = blockIdx.y * 32;
    const int h0 = blockIdx.x * 32;
    const int t  = threadIdx.x;

    {
        const int cl = t >> 3, h4 = (t & 7) * 4;
        float4 v = *(const float4*)(fm + ((size_t)(b*256 + c0 + cl)) * HWSZ + h0 + h4);
        ts[h4+0][cl] = v.x; ts[h4+1][cl] = v.y; ts[h4+2][cl] = v.z; ts[h4+3][cl] = v.w;
    }
    __syncthreads();
    {
        const int hl = t >> 3, c4 = (t & 7) * 4;
        float4 o = make_float4(ts[hl][c4], ts[hl][c4+1], ts[hl][c4+2], ts[hl][c4+3]);
        *(float4*)(fmT + ((size_t)((b << 14) + h0 + hl)) * 256 + c0 + c4) = o;
    }
}

// ---------------- FP16 tensor-core GEMM --------------------------------------
// C[M,N] = A[M,K] @ W[K,N] + bias, optional relu, optional row mask.
// BM=128, BN=128, BK=32; 256 threads = 8 warps (4 m x 2 n); warp tile 32x64.
// Inputs fp32 in gmem, converted to fp16 on the smem store; fp32 accumulate.
// MODE 0: A(m,k) = A0[m*K+k]
// MODE 2: A(m,k) = k<256 ? A0[m*256+k] : A1[m*256+k-256]
#define LDAH 40     // half stride, 5x16B units -> LDSM conflict-free
#define LDBH 136    // half stride, 17x16B units -> LDSM conflict-free
template<int MODE>
__global__ void __launch_bounds__(256)
gemm_h(const float* __restrict__ A0, const float* __restrict__ A1,
       const float* __restrict__ Wm, const float* __restrict__ Bias,
       float* __restrict__ C, int M, int N, int K,
       int doRelu, const int* __restrict__ mask)
{
    __shared__ __half As[2][128 * LDAH];
    __shared__ __half Bs[2][32 * LDBH];

    const int t    = threadIdx.x;
    const int m0   = blockIdx.y * 128;
    const int n0   = blockIdx.x * 128;
    const int wid  = t >> 5;
    const int lane = t & 31;
    const int wm   = wid >> 1;          // 0..3 -> 32-row band
    const int wn   = wid & 1;           // 0..1 -> 64-col band
    const int g    = lane >> 2;         // 0..7
    const int tig  = lane & 3;          // 0..3

    float acc[2][8][4];
#pragma unroll
    for (int i=0;i<2;i++)
#pragma unroll
        for (int j=0;j<8;j++)
#pragma unroll
            for (int l=0;l<4;l++) acc[i][j][l] = 0.f;

    float4 av[4], bv[4];

    auto g2r = [&](int k0) {
#pragma unroll
        for (int i = 0; i < 4; i++) {
            const int idx = t + i * 256;        // 0..1023
            const int m   = idx >> 3;           // 0..127
            const int k4  = (idx & 7) * 4;      // 0..28
            const int kg  = k0 + k4;
            const float* src;
            if (MODE == 2) src = (kg < 256) ? (A0 + (size_t)(m0+m)*256 + kg)
                                            : (A1 + (size_t)(m0+m)*256 + (kg-256));
            else           src = A0 + (size_t)(m0+m)*K + kg;
            av[i] = *(const float4*)src;
        }
#pragma unroll
        for (int i = 0; i < 4; i++) {
            const int idx = t + i * 256;
            const int kr  = idx >> 5;           // 0..31
            const int n4  = (idx & 31) * 4;     // 0..124
            bv[i] = *(const float4*)(Wm + (size_t)(k0+kr)*N + n0 + n4);
        }
    };
    auto r2s = [&](int s) {
#pragma unroll
        for (int i = 0; i < 4; i++) {
            const int idx = t + i * 256;
            const int m   = idx >> 3;
            const int k4  = (idx & 7) * 4;
            __half2* d = (__half2*)&As[s][m*LDAH + k4];
            d[0] = __floats2half2_rn(av[i].x, av[i].y);
            d[1] = __floats2half2_rn(av[i].z, av[i].w);
        }
#pragma unroll
        for (int i = 0; i < 4; i++) {
            const int idx = t + i * 256;
            const int kr  = idx >> 5;
            const int n4  = (idx & 31) * 4;
            __half2* d = (__half2*)&Bs[s][kr*LDBH + n4];
            d[0] = __floats2half2_rn(bv[i].x, bv[i].y);
            d[1] = __floats2half2_rn(bv[i].z, bv[i].w);
        }
    };
    auto compute = [&](int s) {
#pragma unroll
        for (int ks = 0; ks < 2; ks++) {
            const int k = ks * 16;
            unsigned a[2][4], b[8][2];
#pragma unroll
            for (int mt = 0; mt < 2; mt++) {
                const int row = wm*32 + mt*16 + (lane & 15);
                const int col = k + ((lane >> 4) << 3);
                unsigned addr = (unsigned)__cvta_generic_to_shared(&As[s][row*LDAH + col]);
                ldsm4(a[mt][0], a[mt][1], a[mt][2], a[mt][3], addr);
            }
#pragma unroll
            for (int p = 0; p < 4; p++) {
                const int rowB = k + (lane & 15);
                const int colB = wn*64 + p*16 + ((lane >> 4) << 3);
                unsigned addr = (unsigned)__cvta_generic_to_shared(&Bs[s][rowB*LDBH + colB]);
                ldsm4t(b[2*p][0], b[2*p][1], b[2*p+1][0], b[2*p+1][1], addr);
            }
#pragma unroll
            for (int mt = 0; mt < 2; mt++)
#pragma unroll
                for (int nt = 0; nt < 8; nt++)
                    hmma16(acc[mt][nt], a[mt][0], a[mt][1], a[mt][2], a[mt][3],
                           b[nt][0], b[nt][1]);
        }
    };

    const int nK = K / 32;
    g2r(0);
    r2s(0);
    __syncthreads();
    for (int it = 0; it < nK; ++it) {
        if (it + 1 < nK) g2r((it+1) * 32);
        compute(it & 1);
        if (it + 1 < nK) {
            __syncthreads();
            r2s((it+1) & 1);
            __syncthreads();
        }
    }

    // ---- epilogue ----
#pragma unroll
    for (int mt = 0; mt < 2; mt++) {
        const int r0 = m0 + wm*32 + mt*16 + g;
        const int r1 = r0 + 8;
        const float msk0 = mask ? (mask[r0] ? 1.f : 0.f) : 1.f;
        const float msk1 = mask ? (mask[r1] ? 1.f : 0.f) : 1.f;
#pragma unroll
        for (int nt = 0; nt < 8; nt++) {
            const int c = n0 + wn*64 + nt*8 + tig*2;
            const float b0 = Bias[c], b1 = Bias[c+1];
            float v00 = acc[mt][nt][0] + b0, v01 = acc[mt][nt][1] + b1;
            float v10 = acc[mt][nt][2] + b0, v11 = acc[mt][nt][3] + b1;
            if (doRelu) {
                v00 = fmaxf(v00, 0.f); v01 = fmaxf(v01, 0.f);
                v10 = fmaxf(v10, 0.f); v11 = fmaxf(v11, 0.f);
            }
            *(float2*)(C + (size_t)r0*N + c) = make_float2(v00*msk0, v01*msk0);
            *(float2*)(C + (size_t)r1*N + c) = make_float2(v10*msk1, v11*msk1);
        }
    }
}

// ------------- offsets + softmax weights: one THREAD per query ---------------
// Weights staged once in smem (broadcast reads), q staged in padded smem chunks.
__global__ void __launch_bounds__(256)
offw2_kernel(const float* __restrict__ q,
             const float* __restrict__ Wo, const float* __restrict__ bo,
             const float* __restrict__ Ww, const float* __restrict__ bw,
             const float* __restrict__ ref, float* __restrict__ samp)
{
    __shared__ float wcat[256*12];       // [k][12]: Wo row then Ww row
    __shared__ float qs[256*33];         // [row][k%32], pad 33 -> conflict-free

    const int t  = threadIdx.x;
    const int q0 = blockIdx.x * 256;

    {   // stage weights: thread t handles k-row t
        float4 w0 = *(const float4*)(Wo + t*8);
        float4 w1 = *(const float4*)(Wo + t*8 + 4);
        float4 w2 = *(const float4*)(Ww + t*4);
        *(float4*)&wcat[t*12 + 0] = w0;
        *(float4*)&wcat[t*12 + 4] = w1;
        *(float4*)&wcat[t*12 + 8] = w2;
    }

    float acc[12];
#pragma unroll
    for (int j = 0; j < 12; j++) acc[j] = 0.f;

    for (int k0 = 0; k0 < 256; k0 += 32) {
        __syncthreads();
#pragma unroll
        for (int i = 0; i < 8; i++) {
            const int idx4 = i*256 + t;          // 0..2047 float4s
            const int row  = idx4 >> 3;          // 0..255
            const int c4   = (idx4 & 7) * 4;     // 0..28
            float4 v = *(const float4*)(q + (size_t)(q0+row)*256 + k0 + c4);
            qs[row*33 + c4 + 0] = v.x; qs[row*33 + c4 + 1] = v.y;
            qs[row*33 + c4 + 2] = v.z; qs[row*33 + c4 + 3] = v.w;
        }
        __syncthreads();
#pragma unroll
        for (int kk = 0; kk < 32; kk++) {
            const float qv = qs[t*33 + kk];
            const float4 w0 = *(const float4*)&wcat[(k0+kk)*12 + 0];
            const float4 w1 = *(const float4*)&wcat[(k0+kk)*12 + 4];
            const float4 w2 = *(const float4*)&wcat[(k0+kk)*12 + 8];
            acc[0] = fmaf(qv, w0.x, acc[0]); acc[1] = fmaf(qv, w0.y, acc[1]);
            acc[2] = fmaf(qv, w0.z, acc[2]); acc[3] = fmaf(qv, w0.w, acc[3]);
            acc[4] = fmaf(qv, w1.x, acc[4]); acc[5] = fmaf(qv, w1.y, acc[5]);
            acc[6] = fmaf(qv, w1.z, acc[6]); acc[7] = fmaf(qv, w1.w, acc[7]);
            acc[8] = fmaf(qv, w2.x, acc[8]); acc[9] = fmaf(qv, w2.y, acc[9]);
            acc[10]= fmaf(qv, w2.z, acc[10]);acc[11]= fmaf(qv, w2.w, acc[11]);
        }
    }

    // postprocess: softmax over acc[8..11], tanh offsets acc[0..7]
    const int qi = q0 + t;
    const float rx = ref[(size_t)qi*2+0];
    const float ry = ref[(size_t)qi*2+1];
    float v[4], mx = -1e30f;
#pragma unroll
    for (int j=0;j<4;j++) { v[j] = acc[8+j] + bw[j]; mx = fmaxf(mx, v[j]); }
    float s = 0.f;
#pragma unroll
    for (int j=0;j<4;j++) { v[j] = __expf(v[j]-mx); s += v[j]; }
    const float inv = 1.f / s;
    float* o = samp + (size_t)qi*12;
#pragma unroll
    for (int sI=0; sI<4; sI++) {
        float ox = tanhf(acc[2*sI+0] + bo[2*sI+0]) * OFFSET_SCALE;
        float oy = tanhf(acc[2*sI+1] + bo[2*sI+1]) * OFFSET_SCALE;
        float gx = fminf(fmaxf(rx + ox, -1.2f), 1.2f);
        float gy = fminf(fmaxf(ry + oy, -1.2f), 1.2f);
        o[sI*3+0] = gx;
        o[sI*3+1] = gy;
        o[sI*3+2] = v[sI]*inv;
    }
}

// ------------- bilinear gather + weighted ctx: 4 queries per block, float4 ---
__global__ void __launch_bounds__(256)
sample2_kernel(const float* __restrict__ pf, const float* __restrict__ samp,
               const int* __restrict__ mask, float* __restrict__ ctx)
{
    __shared__ float sp[48];
    const int t = threadIdx.x;
    if (t < 48) sp[t] = samp[(size_t)blockIdx.x*48 + t];
    __syncthreads();

    const int qi = t >> 6;                 // 0..3
    const int q  = blockIdx.x*4 + qi;
    const int d4 = (t & 63) * 4;

    float4 acc = make_float4(0.f, 0.f, 0.f, 0.f);
    if (mask[q]) {
        const float* base = pf + (((size_t)(q >> 14)) << 14) * 256;
#pragma unroll
        for (int s = 0; s < 4; s++) {
            const float gx = sp[qi*12 + s*3 + 0];
            const float gy = sp[qi*12 + s*3 + 1];
            const float w  = sp[qi*12 + s*3 + 2];
            const float x = (gx + 1.f) * 0.5f * (WW - 1);
            const float y = (gy + 1.f) * 0.5f * (HH - 1);
            const float x0f = floorf(x), y0f = floorf(y);
            const int x0 = (int)x0f, y0 = (int)y0f;
            const float wx1 = x - x0f, wy1 = y - y0f;
            const float wx0 = 1.f - wx1, wy0 = 1.f - wy1;
            const int   xs[2]  = {x0, x0+1};
            const int   ys[2]  = {y0, y0+1};
            const float wxs[2] = {wx0, wx1};
            const float wys[2] = {wy0, wy1};
#pragma unroll
            for (int cy=0; cy<2; cy++)
#pragma unroll
                for (int cx=0; cx<2; cx++) {
                    const int xi = xs[cx], yi = ys[cy];
                    if (xi >= 0 && xi < WW && yi >= 0 && yi < HH) {
                        const float cw = w * wxs[cx] * wys[cy];
                        float4 v = *(const float4*)(base + (((size_t)(yi*WW + xi)) << 8) + d4);
                        acc.x = fmaf(cw, v.x, acc.x);
                        acc.y = fmaf(cw, v.y, acc.y);
                        acc.z = fmaf(cw, v.z, acc.z);
                        acc.w = fmaf(cw, v.w, acc.w);
                    }
                }
        }
    }
    *(float4*)(ctx + (size_t)q*256 + d4) = acc;
}

// -----------------------------------------------------------------------------
extern "C" void kernel_launch(void* const* d_in, const int* in_sizes, int n_in,
                              void* d_out, int out_size)
{
    const float* queries  = (const float*)d_in[0];
    const float* ref_pts  = (const float*)d_in[1];
    const float* fmap     = (const float*)d_in[2];
    const int*   vmask    = (const int*)  d_in[3];
    const float* Wq = (const float*)d_in[4];
    const float* bq = (const float*)d_in[5];
    const float* Wf = (const float*)d_in[6];
    const float* bf = (const float*)d_in[7];
    const float* Wo = (const float*)d_in[8];
    const float* bo = (const float*)d_in[9];
    const float* Ww = (const float*)d_in[10];
    const float* bw = (const float*)d_in[11];
    const float* W1 = (const float*)d_in[12];
    const float* b1 = (const float*)d_in[13];
    const float* W2 = (const float*)d_in[14];
    const float* b2 = (const float*)d_in[15];
    float* out = (float*)d_out;

    float *fmT, *pf, *pq, *ctx, *h1, *samp;
    cudaGetSymbolAddress((void**)&fmT,  g_fmT);
    cudaGetSymbolAddress((void**)&pf,   g_pf);
    cudaGetSymbolAddress((void**)&pq,   g_pq);
    cudaGetSymbolAddress((void**)&ctx,  g_ctx);
    cudaGetSymbolAddress((void**)&h1,   g_h1);
    cudaGetSymbolAddress((void**)&samp, g_samp);

    const dim3 gGemm(256/128, MTOT/128);    // (2, 512)
    const dim3 gTr(HWSZ/32, 256/32, BB);    // (512, 8, 4)

    // 0) fmap CHW -> HWC
    transpose_k<<<gTr, 256>>>(fmap, fmT);
    // 1) pf = conv1x1(fmT, Wf) + bf   (HWC layout)
    gemm_h<0><<<gGemm, 256>>>(fmT, nullptr, Wf, bf, pf, MTOT, 256, 256, 0, nullptr);
    // 2) pq = (queries @ Wq + bq) * mask
    gemm_h<0><<<gGemm, 256>>>(queries, nullptr, Wq, bq, pq, MTOT, 256, 256, 0, vmask);
    // 3) offsets + softmax weights per query
    offw2_kernel<<<MTOT/256, 256>>>(queries, Wo, bo, Ww, bw, ref_pts, samp);
    // 4) bilinear sample + weighted sum -> ctx (masked)
    sample2_kernel<<<MTOT/4, 256>>>(pf, samp, vmask, ctx);
    // 5) h1 = relu([pq|ctx] @ W1 + b1)
    gemm_h<2><<<gGemm, 256>>>(pq, ctx, W1, b1, h1, MTOT, 256, 512, 1, nullptr);
    // 6) out = h1 @ W2 + b2
    gemm_h<0><<<gGemm, 256>>>(h1, nullptr, W2, b2, out, MTOT, 256, 256, 0, nullptr);
}

// round 5
// speedup vs baseline: 4.7225x; 1.1293x over previous
#include <cuda_runtime.h>
#include <cuda_fp16.h>
#include <cuda_bf16.h>
#include <math.h>

// Problem constants
#define BB 4
#define QQ 16384
#define SS 4
#define HD 256
#define HH 128
#define WW 128
#define HWSZ (HH*WW)          // 16384
#define MTOT (BB*QQ)          // 65536
#define OFFSET_SCALE 0.05f

// ---------------- scratch (device globals; no runtime alloc allowed) ----------
__device__ __half g_pf [(size_t)BB*HWSZ*HD];  // pf  HWC fp16   33.5MB
__device__ __half g_pq [(size_t)MTOT*HD];     // masked pq      33.5MB
__device__ __half g_ctx[(size_t)MTOT*HD];     // masked ctx     33.5MB
__device__ __half g_h1 [(size_t)MTOT*HD];     // relu(h@W1+b1)  33.5MB

// ---------------- mma / ldmatrix helpers -------------------------------------
__device__ __forceinline__ void hmma16(float* c,
                                       unsigned a0, unsigned a1, unsigned a2, unsigned a3,
                                       unsigned b0, unsigned b1) {
    asm volatile(
        "mma.sync.aligned.m16n8k16.row.col.f32.f16.f16.f32 "
        "{%0,%1,%2,%3},{%4,%5,%6,%7},{%8,%9},{%0,%1,%2,%3};"
        : "+f"(c[0]), "+f"(c[1]), "+f"(c[2]), "+f"(c[3])
        : "r"(a0), "r"(a1), "r"(a2), "r"(a3), "r"(b0), "r"(b1));
}
__device__ __forceinline__ void ldsm4(unsigned& r0, unsigned& r1, unsigned& r2, unsigned& r3,
                                      unsigned addr) {
    asm volatile("ldmatrix.sync.aligned.m8n8.x4.shared.b16 {%0,%1,%2,%3}, [%4];"
                 : "=r"(r0), "=r"(r1), "=r"(r2), "=r"(r3) : "r"(addr));
}
__device__ __forceinline__ void ldsm4t(unsigned& r0, unsigned& r1, unsigned& r2, unsigned& r3,
                                       unsigned addr) {
    asm volatile("ldmatrix.sync.aligned.m8n8.x4.trans.shared.b16 {%0,%1,%2,%3}, [%4];"
                 : "=r"(r0), "=r"(r1), "=r"(r2), "=r"(r3) : "r"(addr));
}

#define LDAH 40     // m-major A stride (halfs): 5x16B units -> LDSM conflict-free
#define LDBH 136    // k-major stride (halfs): 17x16B units -> LDSM conflict-free

// ---------------- generic GEMM: m-major A smem -------------------------------
// C[M,N] = A[M,K] @ W[K,N] + bias; TA in {float,half}; TC in {float,half}.
// MODE 0: A(m,k) = A0[m*K+k]
// MODE 2: A(m,k) = k<256 ? A0[m*256+k] : A1[m*256+k-256]   (TA=half)
template<int MODE, typename TA, typename TC>
__global__ void __launch_bounds__(256)
gemm_h(const TA* __restrict__ A0, const TA* __restrict__ A1,
       const float* __restrict__ Wm, const float* __restrict__ Bias,
       TC* __restrict__ C, int M, int N, int K,
       int doRelu, const int* __restrict__ mask)
{
    constexpr bool AH = (sizeof(TA) == 2);
    __shared__ __half As[2][128 * LDAH];
    __shared__ __half Bs[2][32 * LDBH];

    const int t    = threadIdx.x;
    const int m0   = blockIdx.y * 128;
    const int n0   = blockIdx.x * 128;
    const int wid  = t >> 5;
    const int lane = t & 31;
    const int wm   = wid >> 1;
    const int wn   = wid & 1;
    const int g    = lane >> 2;
    const int tig  = lane & 3;

    float acc[2][8][4];
#pragma unroll
    for (int i=0;i<2;i++)
#pragma unroll
        for (int j=0;j<8;j++)
#pragma unroll
            for (int l=0;l<4;l++) acc[i][j][l] = 0.f;

    float4 av[4]; uint4 avh[2]; float4 bv[4];

    auto g2r = [&](int k0) {
        if constexpr (AH) {
#pragma unroll
            for (int i = 0; i < 2; i++) {
                const int idx = t + i * 256;        // 0..511 uint4s
                const int m   = idx >> 2;           // 0..127
                const int k8  = (idx & 3) * 8;      // 0..24
                const int kg  = k0 + k8;
                const __half* src;
                if (MODE == 2) src = (kg < 256) ? ((const __half*)A0 + (size_t)(m0+m)*256 + kg)
                                                : ((const __half*)A1 + (size_t)(m0+m)*256 + (kg-256));
                else           src = (const __half*)A0 + (size_t)(m0+m)*K + kg;
                avh[i] = *(const uint4*)src;
            }
        } else {
#pragma unroll
            for (int i = 0; i < 4; i++) {
                const int idx = t + i * 256;
                const int m   = idx >> 3;
                const int k4  = (idx & 7) * 4;
                const float* src = (const float*)A0 + (size_t)(m0+m)*K + k0 + k4;
                av[i] = *(const float4*)src;
            }
        }
#pragma unroll
        for (int i = 0; i < 4; i++) {
            const int idx = t + i * 256;
            const int kr  = idx >> 5;
            const int n4  = (idx & 31) * 4;
            bv[i] = *(const float4*)(Wm + (size_t)(k0+kr)*N + n0 + n4);
        }
    };
    auto r2s = [&](int s) {
        if constexpr (AH) {
#pragma unroll
            for (int i = 0; i < 2; i++) {
                const int idx = t + i * 256;
                const int m   = idx >> 2;
                const int k8  = (idx & 3) * 8;
                *(uint4*)&As[s][m*LDAH + k8] = avh[i];
            }
        } else {
#pragma unroll
            for (int i = 0; i < 4; i++) {
                const int idx = t + i * 256;
                const int m   = idx >> 3;
                const int k4  = (idx & 7) * 4;
                __half2* d = (__half2*)&As[s][m*LDAH + k4];
                d[0] = __floats2half2_rn(av[i].x, av[i].y);
                d[1] = __floats2half2_rn(av[i].z, av[i].w);
            }
        }
#pragma unroll
        for (int i = 0; i < 4; i++) {
            const int idx = t + i * 256;
            const int kr  = idx >> 5;
            const int n4  = (idx & 31) * 4;
            __half2* d = (__half2*)&Bs[s][kr*LDBH + n4];
            d[0] = __floats2half2_rn(bv[i].x, bv[i].y);
            d[1] = __floats2half2_rn(bv[i].z, bv[i].w);
        }
    };
    auto compute = [&](int s) {
#pragma unroll
        for (int ks = 0; ks < 2; ks++) {
            const int k = ks * 16;
            unsigned a[2][4], b[8][2];
#pragma unroll
            for (int mt = 0; mt < 2; mt++) {
                const int row = wm*32 + mt*16 + (lane & 15);
                const int col = k + ((lane >> 4) << 3);
                unsigned addr = (unsigned)__cvta_generic_to_shared(&As[s][row*LDAH + col]);
                ldsm4(a[mt][0], a[mt][1], a[mt][2], a[mt][3], addr);
            }
#pragma unroll
            for (int p = 0; p < 4; p++) {
                const int rowB = k + (lane & 15);
                const int colB = wn*64 + p*16 + ((lane >> 4) << 3);
                unsigned addr = (unsigned)__cvta_generic_to_shared(&Bs[s][rowB*LDBH + colB]);
                ldsm4t(b[2*p][0], b[2*p][1], b[2*p+1][0], b[2*p+1][1], addr);
            }
#pragma unroll
            for (int mt = 0; mt < 2; mt++)
#pragma unroll
                for (int nt = 0; nt < 8; nt++)
                    hmma16(acc[mt][nt], a[mt][0], a[mt][1], a[mt][2], a[mt][3],
                           b[nt][0], b[nt][1]);
        }
    };

    const int nK = K / 32;
    g2r(0);
    r2s(0);
    __syncthreads();
    for (int it = 0; it < nK; ++it) {
        if (it + 1 < nK) g2r((it+1) * 32);
        compute(it & 1);
        if (it + 1 < nK) {
            __syncthreads();
            r2s((it+1) & 1);
            __syncthreads();
        }
    }

    // ---- epilogue ----
#pragma unroll
    for (int mt = 0; mt < 2; mt++) {
        const int r0 = m0 + wm*32 + mt*16 + g;
        const int r1 = r0 + 8;
        const float msk0 = mask ? (mask[r0] ? 1.f : 0.f) : 1.f;
        const float msk1 = mask ? (mask[r1] ? 1.f : 0.f) : 1.f;
#pragma unroll
        for (int nt = 0; nt < 8; nt++) {
            const int c = n0 + wn*64 + nt*8 + tig*2;
            const float b0 = Bias[c], b1 = Bias[c+1];
            float v00 = acc[mt][nt][0] + b0, v01 = acc[mt][nt][1] + b1;
            float v10 = acc[mt][nt][2] + b0, v11 = acc[mt][nt][3] + b1;
            if (doRelu) {
                v00 = fmaxf(v00, 0.f); v01 = fmaxf(v01, 0.f);
                v10 = fmaxf(v10, 0.f); v11 = fmaxf(v11, 0.f);
            }
            v00 *= msk0; v01 *= msk0; v10 *= msk1; v11 *= msk1;
            if constexpr (sizeof(TC) == 2) {
                *(__half2*)((__half*)C + (size_t)r0*N + c) = __floats2half2_rn(v00, v01);
                *(__half2*)((__half*)C + (size_t)r1*N + c) = __floats2half2_rn(v10, v11);
            } else {
                *(float2*)((float*)C + (size_t)r0*N + c) = make_float2(v00, v01);
                *(float2*)((float*)C + (size_t)r1*N + c) = make_float2(v10, v11);
            }
        }
    }
}

// ---------------- pf GEMM: A read directly from CHW feature map --------------
// A(m,k) = fmap[((m>>14)*256 + k)*16384 + (m&16383)]; coalesced along m.
// As stored k-major [32][LDBH]; A fragments via ldmatrix.trans.
__global__ void __launch_bounds__(256)
gemm_pf(const float* __restrict__ fm, const float* __restrict__ Wm,
        const float* __restrict__ Bias, __half* __restrict__ C, int N)
{
    __shared__ __half As[2][32 * LDBH];
    __shared__ __half Bs[2][32 * LDBH];

    const int t    = threadIdx.x;
    const int m0   = blockIdx.y * 128;
    const int n0   = blockIdx.x * 128;
    const int wid  = t >> 5;
    const int lane = t & 31;
    const int wm   = wid >> 1;
    const int wn   = wid & 1;
    const int g    = lane >> 2;
    const int tig  = lane & 3;

    const int b    = m0 >> 14;
    const int mlow = m0 & (HWSZ - 1);

    float acc[2][8][4];
#pragma unroll
    for (int i=0;i<2;i++)
#pragma unroll
        for (int j=0;j<8;j++)
#pragma unroll
            for (int l=0;l<4;l++) acc[i][j][l] = 0.f;

    float4 av[4], bv[4];

    auto g2r = [&](int k0) {
#pragma unroll
        for (int i = 0; i < 4; i++) {
            const int idx = t + i * 256;        // 0..1023
            const int kr  = idx >> 5;           // 0..31
            const int m4  = (idx & 31) * 4;     // 0..124
            av[i] = *(const float4*)(fm + ((size_t)(b*256 + k0 + kr))*HWSZ + mlow + m4);
        }
#pragma unroll
        for (int i = 0; i < 4; i++) {
            const int idx = t + i * 256;
            const int kr  = idx >> 5;
            const int n4  = (idx & 31) * 4;
            bv[i] = *(const float4*)(Wm + (size_t)(k0+kr)*N + n0 + n4);
        }
    };
    auto r2s = [&](int s) {
#pragma unroll
        for (int i = 0; i < 4; i++) {
            const int idx = t + i * 256;
            const int kr  = idx >> 5;
            const int m4  = (idx & 31) * 4;
            __half2* d = (__half2*)&As[s][kr*LDBH + m4];
            d[0] = __floats2half2_rn(av[i].x, av[i].y);
            d[1] = __floats2half2_rn(av[i].z, av[i].w);
        }
#pragma unroll
        for (int i = 0; i < 4; i++) {
            const int idx = t + i * 256;
            const int kr  = idx >> 5;
            const int n4  = (idx & 31) * 4;
            __half2* d = (__half2*)&Bs[s][kr*LDBH + n4];
            d[0] = __floats2half2_rn(bv[i].x, bv[i].y);
            d[1] = __floats2half2_rn(bv[i].z, bv[i].w);
        }
    };
    auto compute = [&](int s) {
#pragma unroll
        for (int ks = 0; ks < 2; ks++) {
            const int k = ks * 16;
            unsigned a[2][4], bfrag[8][2];
            // A fragments via trans: group0 = m0-7 x k0-7, g1 = m8-15 x k0-7,
            // g2 = m0-7 x k8-15, g3 = m8-15 x k8-15.
            const int krl = k + (lane & 7) + ((lane >> 4) << 3);
            const int mcl = ((lane >> 3) & 1) * 8;
#pragma unroll
            for (int mt = 0; mt < 2; mt++) {
                const int mBase = wm*32 + mt*16;
                unsigned addr = (unsigned)__cvta_generic_to_shared(
                    &As[s][krl*LDBH + mBase + mcl]);
                ldsm4t(a[mt][0], a[mt][1], a[mt][2], a[mt][3], addr);
            }
#pragma unroll
            for (int p = 0; p < 4; p++) {
                const int rowB = k + (lane & 15);
                const int colB = wn*64 + p*16 + ((lane >> 4) << 3);
                unsigned addr = (unsigned)__cvta_generic_to_shared(&Bs[s][rowB*LDBH + colB]);
                ldsm4t(bfrag[2*p][0], bfrag[2*p][1], bfrag[2*p+1][0], bfrag[2*p+1][1], addr);
            }
#pragma unroll
            for (int mt = 0; mt < 2; mt++)
#pragma unroll
                for (int nt = 0; nt < 8; nt++)
                    hmma16(acc[mt][nt], a[mt][0], a[mt][1], a[mt][2], a[mt][3],
                           bfrag[nt][0], bfrag[nt][1]);
        }
    };

    const int nK = 256 / 32;
    g2r(0);
    r2s(0);
    __syncthreads();
    for (int it = 0; it < nK; ++it) {
        if (it + 1 < nK) g2r((it+1) * 32);
        compute(it & 1);
        if (it + 1 < nK) {
            __syncthreads();
            r2s((it+1) & 1);
            __syncthreads();
        }
    }

#pragma unroll
    for (int mt = 0; mt < 2; mt++) {
        const int r0 = m0 + wm*32 + mt*16 + g;
        const int r1 = r0 + 8;
#pragma unroll
        for (int nt = 0; nt < 8; nt++) {
            const int c = n0 + wn*64 + nt*8 + tig*2;
            const float b0 = Bias[c], b1 = Bias[c+1];
            *(__half2*)(C + (size_t)r0*N + c) =
                __floats2half2_rn(acc[mt][nt][0] + b0, acc[mt][nt][1] + b1);
            *(__half2*)(C + (size_t)r1*N + c) =
                __floats2half2_rn(acc[mt][nt][2] + b0, acc[mt][nt][3] + b1);
        }
    }
}

// ---------------- fused offsets + softmax + bilinear gather ------------------
// One warp per query; QPW queries per warp sequentially.
#define QPW 4
__global__ void __launch_bounds__(256)
sample3_kernel(const __half* __restrict__ pf, const float* __restrict__ q,
               const float* __restrict__ Wo, const float* __restrict__ bo,
               const float* __restrict__ Ww, const float* __restrict__ bw,
               const float* __restrict__ ref, const int* __restrict__ mask,
               __half* __restrict__ ctx)
{
    __shared__ float wT[12][260];        // transposed weights; stride 260 -> conflict-free
    const int t = threadIdx.x;
    {
        const int k = t;                 // 256 threads, one k-row each
#pragma unroll
        for (int j=0;j<8;j++) wT[j][k]   = Wo[k*8+j];
#pragma unroll
        for (int j=0;j<4;j++) wT[8+j][k] = Ww[k*4+j];
    }
    __syncthreads();

    const int wid = t >> 5, lane = t & 31;
    const int d = lane * 8;              // 8 fp16 channels per lane

    for (int itq = 0; itq < QPW; itq++) {
        const int qi = (blockIdx.x * 8 + wid) * QPW + itq;

        if (!mask[qi]) {
            uint4 z = make_uint4(0,0,0,0);
            *(uint4*)(ctx + (size_t)qi*256 + d) = z;
            continue;
        }

        // ---- 12 logits: q[qi] . [Wo|Ww] ----
        float qv[8];
#pragma unroll
        for (int i=0;i<8;i++) qv[i] = q[(size_t)qi*256 + lane + 32*i];
        float acc[12];
#pragma unroll
        for (int j=0;j<12;j++) {
            float a = 0.f;
#pragma unroll
            for (int i=0;i<8;i++) a = fmaf(qv[i], wT[j][lane + 32*i], a);
            acc[j] = a;
        }
#pragma unroll
        for (int j=0;j<12;j++)
#pragma unroll
            for (int o=16;o;o>>=1) acc[j] += __shfl_xor_sync(0xffffffffu, acc[j], o);

        // ---- softmax + tanh (redundant in all lanes) ----
        const float rx = ref[(size_t)qi*2+0];
        const float ry = ref[(size_t)qi*2+1];
        float v[4], mx = -1e30f;
#pragma unroll
        for (int j=0;j<4;j++) { v[j] = acc[8+j] + bw[j]; mx = fmaxf(mx, v[j]); }
        float sm = 0.f;
#pragma unroll
        for (int j=0;j<4;j++) { v[j] = __expf(v[j]-mx); sm += v[j]; }
        const float inv = 1.f / sm;

        // ---- gather ----
        const __half* base = pf + ((((size_t)(qi >> 14)) << 14)) * 256;
        float a8[8] = {0.f,0.f,0.f,0.f,0.f,0.f,0.f,0.f};
#pragma unroll
        for (int s = 0; s < 4; s++) {
            const float ox = tanhf(acc[2*s+0] + bo[2*s+0]) * OFFSET_SCALE;
            const float oy = tanhf(acc[2*s+1] + bo[2*s+1]) * OFFSET_SCALE;
            const float gx = fminf(fmaxf(rx + ox, -1.2f), 1.2f);
            const float gy = fminf(fmaxf(ry + oy, -1.2f), 1.2f);
            const float w  = v[s] * inv;
            const float x = (gx + 1.f) * 0.5f * (WW - 1);
            const float y = (gy + 1.f) * 0.5f * (HH - 1);
            const float x0f = floorf(x), y0f = floorf(y);
            const int x0 = (int)x0f, y0 = (int)y0f;
            const float wx1 = x - x0f, wy1 = y - y0f;
            const float wx0 = 1.f - wx1, wy0 = 1.f - wy1;
            const int   xs[2]  = {x0, x0+1};
            const int   ys[2]  = {y0, y0+1};
            const float wxs[2] = {wx0, wx1};
            const float wys[2] = {wy0, wy1};
#pragma unroll
            for (int cy=0; cy<2; cy++)
#pragma unroll
                for (int cx=0; cx<2; cx++) {
                    const int xi = xs[cx], yi = ys[cy];
                    if (xi >= 0 && xi < WW && yi >= 0 && yi < HH) {
                        const float cw = w * wxs[cx] * wys[cy];
                        const uint4 vv = *(const uint4*)(base + ((size_t)(yi*WW + xi))*256 + d);
                        const __half2* h = (const __half2*)&vv;
#pragma unroll
                        for (int p = 0; p < 4; p++) {
                            float2 f = __half22float2(h[p]);
                            a8[2*p+0] = fmaf(cw, f.x, a8[2*p+0]);
                            a8[2*p+1] = fmaf(cw, f.y, a8[2*p+1]);
                        }
                    }
                }
        }

        __half2 o0 = __floats2half2_rn(a8[0], a8[1]);
        __half2 o1 = __floats2half2_rn(a8[2], a8[3]);
        __half2 o2 = __floats2half2_rn(a8[4], a8[5]);
        __half2 o3 = __floats2half2_rn(a8[6], a8[7]);
        uint4 o;
        o.x = *(unsigned*)&o0; o.y = *(unsigned*)&o1;
        o.z = *(unsigned*)&o2; o.w = *(unsigned*)&o3;
        *(uint4*)(ctx + (size_t)qi*256 + d) = o;
    }
}

// -----------------------------------------------------------------------------
extern "C" void kernel_launch(void* const* d_in, const int* in_sizes, int n_in,
                              void* d_out, int out_size)
{
    const float* queries  = (const float*)d_in[0];
    const float* ref_pts  = (const float*)d_in[1];
    const float* fmap     = (const float*)d_in[2];
    const int*   vmask    = (const int*)  d_in[3];
    const float* Wq = (const float*)d_in[4];
    const float* bq = (const float*)d_in[5];
    const float* Wf = (const float*)d_in[6];
    const float* bf = (const float*)d_in[7];
    const float* Wo = (const float*)d_in[8];
    const float* bo = (const float*)d_in[9];
    const float* Ww = (const float*)d_in[10];
    const float* bw = (const float*)d_in[11];
    const float* W1 = (const float*)d_in[12];
    const float* b1 = (const float*)d_in[13];
    const float* W2 = (const float*)d_in[14];
    const float* b2 = (const float*)d_in[15];
    float* out = (float*)d_out;

    __half *pfh, *pqh, *ctxh, *h1h;
    cudaGetSymbolAddress((void**)&pfh,  g_pf);
    cudaGetSymbolAddress((void**)&pqh,  g_pq);
    cudaGetSymbolAddress((void**)&ctxh, g_ctx);
    cudaGetSymbolAddress((void**)&h1h,  g_h1);

    const dim3 gGemm(256/128, MTOT/128);    // (2, 512)

    // 1) pf = conv1x1(fmap CHW, Wf) + bf   -> fp16 HWC
    gemm_pf<<<gGemm, 256>>>(fmap, Wf, bf, pfh, 256);
    // 2) pq = (queries @ Wq + bq) * mask   -> fp16
    gemm_h<0, float, __half><<<gGemm, 256>>>(queries, nullptr, Wq, bq, pqh,
                                             MTOT, 256, 256, 0, vmask);
    // 3) fused offsets+softmax+gather -> ctx fp16 (masked)
    sample3_kernel<<<MTOT/(8*QPW), 256>>>(pfh, queries, Wo, bo, Ww, bw,
                                          ref_pts, vmask, ctxh);
    // 4) h1 = relu([pq|ctx] @ W1 + b1)     -> fp16
    gemm_h<2, __half, __half><<<gGemm, 256>>>(pqh, ctxh, W1, b1, h1h,
                                              MTOT, 256, 512, 1, nullptr);
    // 5) out = h1 @ W2 + b2                -> fp32
    gemm_h<0, __half, float><<<gGemm, 256>>>(h1h, nullptr, W2, b2, out,
                                             MTOT, 256, 256, 0, nullptr);
}

// round 6
// speedup vs baseline: 4.8838x; 1.0342x over previous
#include <cuda_runtime.h>
#include <cuda_fp16.h>
#include <cuda_bf16.h>
#include <math.h>

// Problem constants
#define BB 4
#define QQ 16384
#define SS 4
#define HD 256
#define HH 128
#define WW 128
#define HWSZ (HH*WW)          // 16384
#define MTOT (BB*QQ)          // 65536
#define OFFSET_SCALE 0.05f

// ---------------- scratch (device globals; no runtime alloc allowed) ----------
__device__ __half g_pf [(size_t)BB*HWSZ*HD];  // pf  HWC fp16   33.5MB
__device__ __half g_pq [(size_t)MTOT*HD];     // masked pq      33.5MB
__device__ __half g_ctx[(size_t)MTOT*HD];     // masked ctx     33.5MB
__device__ __half g_h1 [(size_t)MTOT*HD];     // relu(h@W1+b1)  33.5MB
__device__ __half g_Wqh[256*256];
__device__ __half g_Wfh[256*256];
__device__ __half g_W1h[512*256];
__device__ __half g_W2h[256*256];

// ---------------- mma / ldmatrix / cp.async helpers --------------------------
__device__ __forceinline__ void hmma16(float* c,
                                       unsigned a0, unsigned a1, unsigned a2, unsigned a3,
                                       unsigned b0, unsigned b1) {
    asm volatile(
        "mma.sync.aligned.m16n8k16.row.col.f32.f16.f16.f32 "
        "{%0,%1,%2,%3},{%4,%5,%6,%7},{%8,%9},{%0,%1,%2,%3};"
        : "+f"(c[0]), "+f"(c[1]), "+f"(c[2]), "+f"(c[3])
        : "r"(a0), "r"(a1), "r"(a2), "r"(a3), "r"(b0), "r"(b1));
}
__device__ __forceinline__ void ldsm4(unsigned& r0, unsigned& r1, unsigned& r2, unsigned& r3,
                                      unsigned addr) {
    asm volatile("ldmatrix.sync.aligned.m8n8.x4.shared.b16 {%0,%1,%2,%3}, [%4];"
                 : "=r"(r0), "=r"(r1), "=r"(r2), "=r"(r3) : "r"(addr));
}
__device__ __forceinline__ void ldsm4t(unsigned& r0, unsigned& r1, unsigned& r2, unsigned& r3,
                                       unsigned addr) {
    asm volatile("ldmatrix.sync.aligned.m8n8.x4.trans.shared.b16 {%0,%1,%2,%3}, [%4];"
                 : "=r"(r0), "=r"(r1), "=r"(r2), "=r"(r3) : "r"(addr));
}
__device__ __forceinline__ void cp16(void* dst, const void* src) {
    unsigned d = (unsigned)__cvta_generic_to_shared(dst);
    asm volatile("cp.async.cg.shared.global [%0], [%1], 16;" :: "r"(d), "l"(src));
}
__device__ __forceinline__ void cp_commit() { asm volatile("cp.async.commit_group;"); }
__device__ __forceinline__ void cp_wait0()  { asm volatile("cp.async.wait_group 0;"); }

#define LDAH 40     // m-major A stride (halfs): 5x16B units -> LDSM conflict-free
#define LDBH 136    // k-major stride (halfs): 17x16B units -> LDSM conflict-free

// ---------------- weight fp32 -> fp16 converter ------------------------------
__global__ void __launch_bounds__(256)
convw_kernel(const float* __restrict__ Wq, const float* __restrict__ Wf,
             const float* __restrict__ W1, const float* __restrict__ W2,
             __half* __restrict__ oWq, __half* __restrict__ oWf,
             __half* __restrict__ oW1, __half* __restrict__ oW2)
{
    const int bi = blockIdx.x;
    const float* src; __half* dst; int base;
    if      (bi < 64)  { src = Wq; dst = oWq; base = bi; }
    else if (bi < 128) { src = Wf; dst = oWf; base = bi - 64; }
    else if (bi < 256) { src = W1; dst = oW1; base = bi - 128; }
    else               { src = W2; dst = oW2; base = bi - 256; }
    const int idx = base*256 + threadIdx.x;     // float4 index
    float4 v = ((const float4*)src)[idx];
    __half2 h0 = __floats2half2_rn(v.x, v.y);
    __half2 h1 = __floats2half2_rn(v.z, v.w);
    ((__half2*)dst)[idx*2+0] = h0;
    ((__half2*)dst)[idx*2+1] = h1;
}

// ---------------- unified GEMM, cp.async pipeline ----------------------------
// C[M,N] = A[M,K] @ Wh[K,N] + bias; Wh fp16 (pre-converted).
// TA=half: A loaded via cp.async.  TA=float: A LDG->cvt->STS.
// MODE 0: A(m,k) = A0[m*K+k];  MODE 2: A(m,k) = k<256 ? A0 : A1 (both half).
template<int MODE, typename TA, typename TC>
__global__ void __launch_bounds__(256)
gemm_a(const TA* __restrict__ A0, const TA* __restrict__ A1,
       const __half* __restrict__ Wh, const float* __restrict__ Bias,
       TC* __restrict__ C, int M, int N, int K,
       int doRelu, const int* __restrict__ mask)
{
    constexpr bool AH = (sizeof(TA) == 2);
    __shared__ __half As[2][128 * LDAH];
    __shared__ __half Bs[2][32 * LDBH];

    const int t    = threadIdx.x;
    const int m0   = blockIdx.y * 128;
    const int n0   = blockIdx.x * 128;
    const int wid  = t >> 5;
    const int lane = t & 31;
    const int wm   = wid >> 1;
    const int wn   = wid & 1;
    const int g    = lane >> 2;
    const int tig  = lane & 3;

    float acc[2][8][4];
#pragma unroll
    for (int i=0;i<2;i++)
#pragma unroll
        for (int j=0;j<8;j++)
#pragma unroll
            for (int l=0;l<4;l++) acc[i][j][l] = 0.f;

    auto load_tile = [&](int s, int k0) {
        if constexpr (AH) {
#pragma unroll
            for (int i = 0; i < 2; i++) {
                const int idx = t + i * 256;        // 0..511 16B chunks
                const int m   = idx >> 2;           // 0..127
                const int k8  = (idx & 3) * 8;      // 0,8,16,24
                const int kg  = k0 + k8;
                const __half* src;
                if (MODE == 2) src = (kg < 256) ? ((const __half*)A0 + (size_t)(m0+m)*256 + kg)
                                                : ((const __half*)A1 + (size_t)(m0+m)*256 + (kg-256));
                else           src = (const __half*)A0 + (size_t)(m0+m)*K + kg;
                cp16(&As[s][m*LDAH + k8], src);
            }
        } else {
#pragma unroll
            for (int i = 0; i < 4; i++) {
                const int idx = t + i * 256;        // 0..1023
                const int m   = idx >> 3;           // 0..127
                const int k4  = (idx & 7) * 4;      // 0..28
                float4 v = *(const float4*)((const float*)A0 + (size_t)(m0+m)*K + k0 + k4);
                __half2 h0 = __floats2half2_rn(v.x, v.y);
                __half2 h1 = __floats2half2_rn(v.z, v.w);
                __half2* d = (__half2*)&As[s][m*LDAH + k4];
                d[0] = h0; d[1] = h1;
            }
        }
#pragma unroll
        for (int i = 0; i < 2; i++) {
            const int idx = t + i * 256;            // 0..511
            const int kr  = idx >> 4;               // 0..31
            const int n8  = (idx & 15) * 8;         // 0..120
            cp16(&Bs[s][kr*LDBH + n8], Wh + (size_t)(k0+kr)*N + n0 + n8);
        }
        cp_commit();
    };

    auto compute = [&](int s) {
#pragma unroll
        for (int ks = 0; ks < 2; ks++) {
            const int k = ks * 16;
            unsigned a[2][4], b[8][2];
#pragma unroll
            for (int mt = 0; mt < 2; mt++) {
                const int row = wm*32 + mt*16 + (lane & 15);
                const int col = k + ((lane >> 4) << 3);
                unsigned addr = (unsigned)__cvta_generic_to_shared(&As[s][row*LDAH + col]);
                ldsm4(a[mt][0], a[mt][1], a[mt][2], a[mt][3], addr);
            }
#pragma unroll
            for (int p = 0; p < 4; p++) {
                const int rowB = k + (lane & 15);
                const int colB = wn*64 + p*16 + ((lane >> 4) << 3);
                unsigned addr = (unsigned)__cvta_generic_to_shared(&Bs[s][rowB*LDBH + colB]);
                ldsm4t(b[2*p][0], b[2*p][1], b[2*p+1][0], b[2*p+1][1], addr);
            }
#pragma unroll
            for (int mt = 0; mt < 2; mt++)
#pragma unroll
                for (int nt = 0; nt < 8; nt++)
                    hmma16(acc[mt][nt], a[mt][0], a[mt][1], a[mt][2], a[mt][3],
                           b[nt][0], b[nt][1]);
        }
    };

    const int nK = K / 32;
    load_tile(0, 0);
    for (int it = 0; it < nK; ++it) {
        cp_wait0();
        __syncthreads();
        if (it + 1 < nK) load_tile((it+1) & 1, (it+1) * 32);
        compute(it & 1);
    }

    // ---- epilogue ----
#pragma unroll
    for (int mt = 0; mt < 2; mt++) {
        const int r0 = m0 + wm*32 + mt*16 + g;
        const int r1 = r0 + 8;
        const float msk0 = mask ? (mask[r0] ? 1.f : 0.f) : 1.f;
        const float msk1 = mask ? (mask[r1] ? 1.f : 0.f) : 1.f;
#pragma unroll
        for (int nt = 0; nt < 8; nt++) {
            const int c = n0 + wn*64 + nt*8 + tig*2;
            const float b0 = Bias[c], b1 = Bias[c+1];
            float v00 = acc[mt][nt][0] + b0, v01 = acc[mt][nt][1] + b1;
            float v10 = acc[mt][nt][2] + b0, v11 = acc[mt][nt][3] + b1;
            if (doRelu) {
                v00 = fmaxf(v00, 0.f); v01 = fmaxf(v01, 0.f);
                v10 = fmaxf(v10, 0.f); v11 = fmaxf(v11, 0.f);
            }
            v00 *= msk0; v01 *= msk0; v10 *= msk1; v11 *= msk1;
            if constexpr (sizeof(TC) == 2) {
                *(__half2*)((__half*)C + (size_t)r0*N + c) = __floats2half2_rn(v00, v01);
                *(__half2*)((__half*)C + (size_t)r1*N + c) = __floats2half2_rn(v10, v11);
            } else {
                *(float2*)((float*)C + (size_t)r0*N + c) = make_float2(v00, v01);
                *(float2*)((float*)C + (size_t)r1*N + c) = make_float2(v10, v11);
            }
        }
    }
}

// ---------------- pf GEMM: A read directly from CHW feature map --------------
// A(m,k) = fmap[((m>>14)*256 + k)*16384 + (m&16383)]; coalesced along m.
// As stored k-major [32][LDBH]; A fragments via ldmatrix.trans. B via cp.async.
__global__ void __launch_bounds__(256)
gemm_pf(const float* __restrict__ fm, const __half* __restrict__ Wh,
        const float* __restrict__ Bias, __half* __restrict__ C, int N)
{
    __shared__ __half As[2][32 * LDBH];
    __shared__ __half Bs[2][32 * LDBH];

    const int t    = threadIdx.x;
    const int m0   = blockIdx.y * 128;
    const int n0   = blockIdx.x * 128;
    const int wid  = t >> 5;
    const int lane = t & 31;
    const int wm   = wid >> 1;
    const int wn   = wid & 1;
    const int g    = lane >> 2;
    const int tig  = lane & 3;

    const int b    = m0 >> 14;
    const int mlow = m0 & (HWSZ - 1);

    float acc[2][8][4];
#pragma unroll
    for (int i=0;i<2;i++)
#pragma unroll
        for (int j=0;j<8;j++)
#pragma unroll
            for (int l=0;l<4;l++) acc[i][j][l] = 0.f;

    auto load_tile = [&](int s, int k0) {
#pragma unroll
        for (int i = 0; i < 4; i++) {
            const int idx = t + i * 256;        // 0..1023
            const int kr  = idx >> 5;           // 0..31
            const int m4  = (idx & 31) * 4;     // 0..124
            float4 v = *(const float4*)(fm + ((size_t)(b*256 + k0 + kr))*HWSZ + mlow + m4);
            __half2 h0 = __floats2half2_rn(v.x, v.y);
            __half2 h1 = __floats2half2_rn(v.z, v.w);
            __half2* d = (__half2*)&As[s][kr*LDBH + m4];
            d[0] = h0; d[1] = h1;
        }
#pragma unroll
        for (int i = 0; i < 2; i++) {
            const int idx = t + i * 256;
            const int kr  = idx >> 4;
            const int n8  = (idx & 15) * 8;
            cp16(&Bs[s][kr*LDBH + n8], Wh + (size_t)(k0+kr)*N + n0 + n8);
        }
        cp_commit();
    };

    auto compute = [&](int s) {
#pragma unroll
        for (int ks = 0; ks < 2; ks++) {
            const int k = ks * 16;
            unsigned a[2][4], bfrag[8][2];
            const int krl = k + (lane & 7) + ((lane >> 4) << 3);
            const int mcl = ((lane >> 3) & 1) * 8;
#pragma unroll
            for (int mt = 0; mt < 2; mt++) {
                const int mBase = wm*32 + mt*16;
                unsigned addr = (unsigned)__cvta_generic_to_shared(
                    &As[s][krl*LDBH + mBase + mcl]);
                ldsm4t(a[mt][0], a[mt][1], a[mt][2], a[mt][3], addr);
            }
#pragma unroll
            for (int p = 0; p < 4; p++) {
                const int rowB = k + (lane & 15);
                const int colB = wn*64 + p*16 + ((lane >> 4) << 3);
                unsigned addr = (unsigned)__cvta_generic_to_shared(&Bs[s][rowB*LDBH + colB]);
                ldsm4t(bfrag[2*p][0], bfrag[2*p][1], bfrag[2*p+1][0], bfrag[2*p+1][1], addr);
            }
#pragma unroll
            for (int mt = 0; mt < 2; mt++)
#pragma unroll
                for (int nt = 0; nt < 8; nt++)
                    hmma16(acc[mt][nt], a[mt][0], a[mt][1], a[mt][2], a[mt][3],
                           bfrag[nt][0], bfrag[nt][1]);
        }
    };

    const int nK = 256 / 32;
    load_tile(0, 0);
    for (int it = 0; it < nK; ++it) {
        cp_wait0();
        __syncthreads();
        if (it + 1 < nK) load_tile((it+1) & 1, (it+1) * 32);
        compute(it & 1);
    }

#pragma unroll
    for (int mt = 0; mt < 2; mt++) {
        const int r0 = m0 + wm*32 + mt*16 + g;
        const int r1 = r0 + 8;
#pragma unroll
        for (int nt = 0; nt < 8; nt++) {
            const int c = n0 + wn*64 + nt*8 + tig*2;
            const float b0 = Bias[c], b1 = Bias[c+1];
            *(__half2*)(C + (size_t)r0*N + c) =
                __floats2half2_rn(acc[mt][nt][0] + b0, acc[mt][nt][1] + b1);
            *(__half2*)(C + (size_t)r1*N + c) =
                __floats2half2_rn(acc[mt][nt][2] + b0, acc[mt][nt][3] + b1);
        }
    }
}

// ---------------- fused offsets + softmax + bilinear gather ------------------
// One warp per query; QPW queries per warp sequentially.
#define QPW 4
__global__ void __launch_bounds__(256)
sample3_kernel(const __half* __restrict__ pf, const float* __restrict__ q,
               const float* __restrict__ Wo, const float* __restrict__ bo,
               const float* __restrict__ Ww, const float* __restrict__ bw,
               const float* __restrict__ ref, const int* __restrict__ mask,
               __half* __restrict__ ctx)
{
    __shared__ float wT[12][260];
    const int t = threadIdx.x;
    {
        const int k = t;
#pragma unroll
        for (int j=0;j<8;j++) wT[j][k]   = Wo[k*8+j];
#pragma unroll
        for (int j=0;j<4;j++) wT[8+j][k] = Ww[k*4+j];
    }
    __syncthreads();

    const int wid = t >> 5, lane = t & 31;
    const int d = lane * 8;

    for (int itq = 0; itq < QPW; itq++) {
        const int qi = (blockIdx.x * 8 + wid) * QPW + itq;

        if (!mask[qi]) {
            uint4 z = make_uint4(0,0,0,0);
            *(uint4*)(ctx + (size_t)qi*256 + d) = z;
            continue;
        }

        float qv[8];
#pragma unroll
        for (int i=0;i<8;i++) qv[i] = q[(size_t)qi*256 + lane + 32*i];
        float acc[12];
#pragma unroll
        for (int j=0;j<12;j++) {
            float a = 0.f;
#pragma unroll
            for (int i=0;i<8;i++) a = fmaf(qv[i], wT[j][lane + 32*i], a);
            acc[j] = a;
        }
#pragma unroll
        for (int j=0;j<12;j++)
#pragma unroll
            for (int o=16;o;o>>=1) acc[j] += __shfl_xor_sync(0xffffffffu, acc[j], o);

        const float rx = ref[(size_t)qi*2+0];
        const float ry = ref[(size_t)qi*2+1];
        float v[4], mx = -1e30f;
#pragma unroll
        for (int j=0;j<4;j++) { v[j] = acc[8+j] + bw[j]; mx = fmaxf(mx, v[j]); }
        float sm = 0.f;
#pragma unroll
        for (int j=0;j<4;j++) { v[j] = __expf(v[j]-mx); sm += v[j]; }
        const float inv = 1.f / sm;

        const __half* base = pf + ((((size_t)(qi >> 14)) << 14)) * 256;
        float a8[8] = {0.f,0.f,0.f,0.f,0.f,0.f,0.f,0.f};
#pragma unroll
        for (int s = 0; s < 4; s++) {
            const float ox = tanhf(acc[2*s+0] + bo[2*s+0]) * OFFSET_SCALE;
            const float oy = tanhf(acc[2*s+1] + bo[2*s+1]) * OFFSET_SCALE;
            const float gx = fminf(fmaxf(rx + ox, -1.2f), 1.2f);
            const float gy = fminf(fmaxf(ry + oy, -1.2f), 1.2f);
            const float w  = v[s] * inv;
            const float x = (gx + 1.f) * 0.5f * (WW - 1);
            const float y = (gy + 1.f) * 0.5f * (HH - 1);
            const float x0f = floorf(x), y0f = floorf(y);
            const int x0 = (int)x0f, y0 = (int)y0f;
            const float wx1 = x - x0f, wy1 = y - y0f;
            const float wx0 = 1.f - wx1, wy0 = 1.f - wy1;
            const int   xs[2]  = {x0, x0+1};
            const int   ys[2]  = {y0, y0+1};
            const float wxs[2] = {wx0, wx1};
            const float wys[2] = {wy0, wy1};
#pragma unroll
            for (int cy=0; cy<2; cy++)
#pragma unroll
                for (int cx=0; cx<2; cx++) {
                    const int xi = xs[cx], yi = ys[cy];
                    if (xi >= 0 && xi < WW && yi >= 0 && yi < HH) {
                        const float cw = w * wxs[cx] * wys[cy];
                        const uint4 vv = *(const uint4*)(base + ((size_t)(yi*WW + xi))*256 + d);
                        const __half2* h = (const __half2*)&vv;
#pragma unroll
                        for (int p = 0; p < 4; p++) {
                            float2 f = __half22float2(h[p]);
                            a8[2*p+0] = fmaf(cw, f.x, a8[2*p+0]);
                            a8[2*p+1] = fmaf(cw, f.y, a8[2*p+1]);
                        }
                    }
                }
        }

        __half2 o0 = __floats2half2_rn(a8[0], a8[1]);
        __half2 o1 = __floats2half2_rn(a8[2], a8[3]);
        __half2 o2 = __floats2half2_rn(a8[4], a8[5]);
        __half2 o3 = __floats2half2_rn(a8[6], a8[7]);
        uint4 o;
        o.x = *(unsigned*)&o0; o.y = *(unsigned*)&o1;
        o.z = *(unsigned*)&o2; o.w = *(unsigned*)&o3;
        *(uint4*)(ctx + (size_t)qi*256 + d) = o;
    }
}

// -----------------------------------------------------------------------------
extern "C" void kernel_launch(void* const* d_in, const int* in_sizes, int n_in,
                              void* d_out, int out_size)
{
    const float* queries  = (const float*)d_in[0];
    const float* ref_pts  = (const float*)d_in[1];
    const float* fmap     = (const float*)d_in[2];
    const int*   vmask    = (const int*)  d_in[3];
    const float* Wq = (const float*)d_in[4];
    const float* bq = (const float*)d_in[5];
    const float* Wf = (const float*)d_in[6];
    const float* bf = (const float*)d_in[7];
    const float* Wo = (const float*)d_in[8];
    const float* bo = (const float*)d_in[9];
    const float* Ww = (const float*)d_in[10];
    const float* bw = (const float*)d_in[11];
    const float* W1 = (const float*)d_in[12];
    const float* b1 = (const float*)d_in[13];
    const float* W2 = (const float*)d_in[14];
    const float* b2 = (const float*)d_in[15];
    float* out = (float*)d_out;

    __half *pfh, *pqh, *ctxh, *h1h, *Wqh, *Wfh, *W1h, *W2h;
    cudaGetSymbolAddress((void**)&pfh,  g_pf);
    cudaGetSymbolAddress((void**)&pqh,  g_pq);
    cudaGetSymbolAddress((void**)&ctxh, g_ctx);
    cudaGetSymbolAddress((void**)&h1h,  g_h1);
    cudaGetSymbolAddress((void**)&Wqh,  g_Wqh);
    cudaGetSymbolAddress((void**)&Wfh,  g_Wfh);
    cudaGetSymbolAddress((void**)&W1h,  g_W1h);
    cudaGetSymbolAddress((void**)&W2h,  g_W2h);

    const dim3 gGemm(256/128, MTOT/128);    // (2, 512)

    // 0) weights fp32 -> fp16
    convw_kernel<<<320, 256>>>(Wq, Wf, W1, W2, Wqh, Wfh, W1h, W2h);
    // 1) pf = conv1x1(fmap CHW, Wf) + bf   -> fp16 HWC
    gemm_pf<<<gGemm, 256>>>(fmap, Wfh, bf, pfh, 256);
    // 2) pq = (queries @ Wq + bq) * mask   -> fp16
    gemm_a<0, float, __half><<<gGemm, 256>>>(queries, nullptr, Wqh, bq, pqh,
                                             MTOT, 256, 256, 0, vmask);
    // 3) fused offsets+softmax+gather -> ctx fp16 (masked)
    sample3_kernel<<<MTOT/(8*QPW), 256>>>(pfh, queries, Wo, bo, Ww, bw,
                                          ref_pts, vmask, ctxh);
    // 4) h1 = relu([pq|ctx] @ W1 + b1)     -> fp16
    gemm_a<2, __half, __half><<<gGemm, 256>>>(pqh, ctxh, W1h, b1, h1h,
                                              MTOT, 256, 512, 1, nullptr);
    // 5) out = h1 @ W2 + b2                -> fp32
    gemm_a<0, __half, float><<<gGemm, 256>>>(h1h, nullptr, W2h, b2, out,
                                             MTOT, 256, 256, 0, nullptr);
}

// round 7
// speedup vs baseline: 5.1361x; 1.0517x over previous
#include <cuda_runtime.h>
#include <cuda_fp16.h>
#include <cuda_bf16.h>
#include <math.h>

// Problem constants
#define BB 4
#define QQ 16384
#define SS 4
#define HD 256
#define HH 128
#define WW 128
#define HWSZ (HH*WW)          // 16384
#define MTOT (BB*QQ)          // 65536
#define OFFSET_SCALE 0.05f

// ---------------- scratch (device globals; no runtime alloc allowed) ----------
__device__ __half g_pf [(size_t)BB*HWSZ*HD];  // pf  HWC fp16   33.5MB
__device__ __half g_pq [(size_t)MTOT*HD];     // masked pq      33.5MB
__device__ __half g_ctx[(size_t)MTOT*HD];     // masked ctx     33.5MB
__device__ __half g_h1 [(size_t)MTOT*HD];     // relu(h@W1+b1)  33.5MB
__device__ float  g_samp[(size_t)MTOT*12];    // per query: (gx,gy,w)x4  3.1MB
__device__ __half g_Wqh[256*256];
__device__ __half g_Wfh[256*256];
__device__ __half g_W1h[512*256];
__device__ __half g_W2h[256*256];

// ---------------- mma / ldmatrix / cp.async helpers --------------------------
__device__ __forceinline__ void hmma16(float* c,
                                       unsigned a0, unsigned a1, unsigned a2, unsigned a3,
                                       unsigned b0, unsigned b1) {
    asm volatile(
        "mma.sync.aligned.m16n8k16.row.col.f32.f16.f16.f32 "
        "{%0,%1,%2,%3},{%4,%5,%6,%7},{%8,%9},{%0,%1,%2,%3};"
        : "+f"(c[0]), "+f"(c[1]), "+f"(c[2]), "+f"(c[3])
        : "r"(a0), "r"(a1), "r"(a2), "r"(a3), "r"(b0), "r"(b1));
}
__device__ __forceinline__ void ldsm4(unsigned& r0, unsigned& r1, unsigned& r2, unsigned& r3,
                                      unsigned addr) {
    asm volatile("ldmatrix.sync.aligned.m8n8.x4.shared.b16 {%0,%1,%2,%3}, [%4];"
                 : "=r"(r0), "=r"(r1), "=r"(r2), "=r"(r3) : "r"(addr));
}
__device__ __forceinline__ void ldsm4t(unsigned& r0, unsigned& r1, unsigned& r2, unsigned& r3,
                                       unsigned addr) {
    asm volatile("ldmatrix.sync.aligned.m8n8.x4.trans.shared.b16 {%0,%1,%2,%3}, [%4];"
                 : "=r"(r0), "=r"(r1), "=r"(r2), "=r"(r3) : "r"(addr));
}
__device__ __forceinline__ void cp16(void* dst, const void* src) {
    unsigned d = (unsigned)__cvta_generic_to_shared(dst);
    asm volatile("cp.async.cg.shared.global [%0], [%1], 16;" :: "r"(d), "l"(src));
}
__device__ __forceinline__ void cp_commit() { asm volatile("cp.async.commit_group;"); }
__device__ __forceinline__ void cp_wait0()  { asm volatile("cp.async.wait_group 0;"); }

#define LDAH 40     // m-major A stride (halfs): 5x16B units -> LDSM conflict-free
#define LDBH 136    // k-major stride (halfs): 17x16B units -> LDSM conflict-free

// ---------------- weight fp32 -> fp16 converter ------------------------------
__global__ void __launch_bounds__(256)
convw_kernel(const float* __restrict__ Wq, const float* __restrict__ Wf,
             const float* __restrict__ W1, const float* __restrict__ W2,
             __half* __restrict__ oWq, __half* __restrict__ oWf,
             __half* __restrict__ oW1, __half* __restrict__ oW2)
{
    const int bi = blockIdx.x;
    const float* src; __half* dst; int base;
    if      (bi < 64)  { src = Wq; dst = oWq; base = bi; }
    else if (bi < 128) { src = Wf; dst = oWf; base = bi - 64; }
    else if (bi < 256) { src = W1; dst = oW1; base = bi - 128; }
    else               { src = W2; dst = oW2; base = bi - 256; }
    const int idx = base*256 + threadIdx.x;     // float4 index
    float4 v = ((const float4*)src)[idx];
    __half2 h0 = __floats2half2_rn(v.x, v.y);
    __half2 h1 = __floats2half2_rn(v.z, v.w);
    ((__half2*)dst)[idx*2+0] = h0;
    ((__half2*)dst)[idx*2+1] = h1;
}

// ---------------- unified GEMM, cp.async pipeline ----------------------------
// C[M,N] = A[M,K] @ Wh[K,N] + bias; Wh fp16 (pre-converted).
// TA=half: A loaded via cp.async.  TA=float: A LDG->cvt->STS.
// MODE 0: A(m,k) = A0[m*K+k];  MODE 2: A(m,k) = k<256 ? A0 : A1 (both half).
template<int MODE, typename TA, typename TC>
__global__ void __launch_bounds__(256)
gemm_a(const TA* __restrict__ A0, const TA* __restrict__ A1,
       const __half* __restrict__ Wh, const float* __restrict__ Bias,
       TC* __restrict__ C, int M, int N, int K,
       int doRelu, const int* __restrict__ mask)
{
    constexpr bool AH = (sizeof(TA) == 2);
    __shared__ __half As[2][128 * LDAH];
    __shared__ __half Bs[2][32 * LDBH];

    const int t    = threadIdx.x;
    const int m0   = blockIdx.y * 128;
    const int n0   = blockIdx.x * 128;
    const int wid  = t >> 5;
    const int lane = t & 31;
    const int wm   = wid >> 1;
    const int wn   = wid & 1;
    const int g    = lane >> 2;
    const int tig  = lane & 3;

    float acc[2][8][4];
#pragma unroll
    for (int i=0;i<2;i++)
#pragma unroll
        for (int j=0;j<8;j++)
#pragma unroll
            for (int l=0;l<4;l++) acc[i][j][l] = 0.f;

    auto load_tile = [&](int s, int k0) {
        if constexpr (AH) {
#pragma unroll
            for (int i = 0; i < 2; i++) {
                const int idx = t + i * 256;        // 0..511 16B chunks
                const int m   = idx >> 2;           // 0..127
                const int k8  = (idx & 3) * 8;      // 0,8,16,24
                const int kg  = k0 + k8;
                const __half* src;
                if (MODE == 2) src = (kg < 256) ? ((const __half*)A0 + (size_t)(m0+m)*256 + kg)
                                                : ((const __half*)A1 + (size_t)(m0+m)*256 + (kg-256));
                else           src = (const __half*)A0 + (size_t)(m0+m)*K + kg;
                cp16(&As[s][m*LDAH + k8], src);
            }
        } else {
#pragma unroll
            for (int i = 0; i < 4; i++) {
                const int idx = t + i * 256;        // 0..1023
                const int m   = idx >> 3;           // 0..127
                const int k4  = (idx & 7) * 4;      // 0..28
                float4 v = *(const float4*)((const float*)A0 + (size_t)(m0+m)*K + k0 + k4);
                __half2 h0 = __floats2half2_rn(v.x, v.y);
                __half2 h1 = __floats2half2_rn(v.z, v.w);
                __half2* d = (__half2*)&As[s][m*LDAH + k4];
                d[0] = h0; d[1] = h1;
            }
        }
#pragma unroll
        for (int i = 0; i < 2; i++) {
            const int idx = t + i * 256;            // 0..511
            const int kr  = idx >> 4;               // 0..31
            const int n8  = (idx & 15) * 8;         // 0..120
            cp16(&Bs[s][kr*LDBH + n8], Wh + (size_t)(k0+kr)*N + n0 + n8);
        }
        cp_commit();
    };

    auto compute = [&](int s) {
#pragma unroll
        for (int ks = 0; ks < 2; ks++) {
            const int k = ks * 16;
            unsigned a[2][4], b[8][2];
#pragma unroll
            for (int mt = 0; mt < 2; mt++) {
                const int row = wm*32 + mt*16 + (lane & 15);
                const int col = k + ((lane >> 4) << 3);
                unsigned addr = (unsigned)__cvta_generic_to_shared(&As[s][row*LDAH + col]);
                ldsm4(a[mt][0], a[mt][1], a[mt][2], a[mt][3], addr);
            }
#pragma unroll
            for (int p = 0; p < 4; p++) {
                const int rowB = k + (lane & 15);
                const int colB = wn*64 + p*16 + ((lane >> 4) << 3);
                unsigned addr = (unsigned)__cvta_generic_to_shared(&Bs[s][rowB*LDBH + colB]);
                ldsm4t(b[2*p][0], b[2*p][1], b[2*p+1][0], b[2*p+1][1], addr);
            }
#pragma unroll
            for (int mt = 0; mt < 2; mt++)
#pragma unroll
                for (int nt = 0; nt < 8; nt++)
                    hmma16(acc[mt][nt], a[mt][0], a[mt][1], a[mt][2], a[mt][3],
                           b[nt][0], b[nt][1]);
        }
    };

    const int nK = K / 32;
    load_tile(0, 0);
    for (int it = 0; it < nK; ++it) {
        cp_wait0();
        __syncthreads();
        if (it + 1 < nK) load_tile((it+1) & 1, (it+1) * 32);
        compute(it & 1);
    }

    // ---- epilogue ----
#pragma unroll
    for (int mt = 0; mt < 2; mt++) {
        const int r0 = m0 + wm*32 + mt*16 + g;
        const int r1 = r0 + 8;
        const float msk0 = mask ? (mask[r0] ? 1.f : 0.f) : 1.f;
        const float msk1 = mask ? (mask[r1] ? 1.f : 0.f) : 1.f;
#pragma unroll
        for (int nt = 0; nt < 8; nt++) {
            const int c = n0 + wn*64 + nt*8 + tig*2;
            const float b0 = Bias[c], b1 = Bias[c+1];
            float v00 = acc[mt][nt][0] + b0, v01 = acc[mt][nt][1] + b1;
            float v10 = acc[mt][nt][2] + b0, v11 = acc[mt][nt][3] + b1;
            if (doRelu) {
                v00 = fmaxf(v00, 0.f); v01 = fmaxf(v01, 0.f);
                v10 = fmaxf(v10, 0.f); v11 = fmaxf(v11, 0.f);
            }
            v00 *= msk0; v01 *= msk0; v10 *= msk1; v11 *= msk1;
            if constexpr (sizeof(TC) == 2) {
                *(__half2*)((__half*)C + (size_t)r0*N + c) = __floats2half2_rn(v00, v01);
                *(__half2*)((__half*)C + (size_t)r1*N + c) = __floats2half2_rn(v10, v11);
            } else {
                *(float2*)((float*)C + (size_t)r0*N + c) = make_float2(v00, v01);
                *(float2*)((float*)C + (size_t)r1*N + c) = make_float2(v10, v11);
            }
        }
    }
}

// ---------------- pf GEMM: A read directly from CHW feature map --------------
__global__ void __launch_bounds__(256)
gemm_pf(const float* __restrict__ fm, const __half* __restrict__ Wh,
        const float* __restrict__ Bias, __half* __restrict__ C, int N)
{
    __shared__ __half As[2][32 * LDBH];
    __shared__ __half Bs[2][32 * LDBH];

    const int t    = threadIdx.x;
    const int m0   = blockIdx.y * 128;
    const int n0   = blockIdx.x * 128;
    const int wid  = t >> 5;
    const int lane = t & 31;
    const int wm   = wid >> 1;
    const int wn   = wid & 1;
    const int g    = lane >> 2;
    const int tig  = lane & 3;

    const int b    = m0 >> 14;
    const int mlow = m0 & (HWSZ - 1);

    float acc[2][8][4];
#pragma unroll
    for (int i=0;i<2;i++)
#pragma unroll
        for (int j=0;j<8;j++)
#pragma unroll
            for (int l=0;l<4;l++) acc[i][j][l] = 0.f;

    auto load_tile = [&](int s, int k0) {
#pragma unroll
        for (int i = 0; i < 4; i++) {
            const int idx = t + i * 256;        // 0..1023
            const int kr  = idx >> 5;           // 0..31
            const int m4  = (idx & 31) * 4;     // 0..124
            float4 v = *(const float4*)(fm + ((size_t)(b*256 + k0 + kr))*HWSZ + mlow + m4);
            __half2 h0 = __floats2half2_rn(v.x, v.y);
            __half2 h1 = __floats2half2_rn(v.z, v.w);
            __half2* d = (__half2*)&As[s][kr*LDBH + m4];
            d[0] = h0; d[1] = h1;
        }
#pragma unroll
        for (int i = 0; i < 2; i++) {
            const int idx = t + i * 256;
            const int kr  = idx >> 4;
            const int n8  = (idx & 15) * 8;
            cp16(&Bs[s][kr*LDBH + n8], Wh + (size_t)(k0+kr)*N + n0 + n8);
        }
        cp_commit();
    };

    auto compute = [&](int s) {
#pragma unroll
        for (int ks = 0; ks < 2; ks++) {
            const int k = ks * 16;
            unsigned a[2][4], bfrag[8][2];
            const int krl = k + (lane & 7) + ((lane >> 4) << 3);
            const int mcl = ((lane >> 3) & 1) * 8;
#pragma unroll
            for (int mt = 0; mt < 2; mt++) {
                const int mBase = wm*32 + mt*16;
                unsigned addr = (unsigned)__cvta_generic_to_shared(
                    &As[s][krl*LDBH + mBase + mcl]);
                ldsm4t(a[mt][0], a[mt][1], a[mt][2], a[mt][3], addr);
            }
#pragma unroll
            for (int p = 0; p < 4; p++) {
                const int rowB = k + (lane & 15);
                const int colB = wn*64 + p*16 + ((lane >> 4) << 3);
                unsigned addr = (unsigned)__cvta_generic_to_shared(&Bs[s][rowB*LDBH + colB]);
                ldsm4t(bfrag[2*p][0], bfrag[2*p][1], bfrag[2*p+1][0], bfrag[2*p+1][1], addr);
            }
#pragma unroll
            for (int mt = 0; mt < 2; mt++)
#pragma unroll
                for (int nt = 0; nt < 8; nt++)
                    hmma16(acc[mt][nt], a[mt][0], a[mt][1], a[mt][2], a[mt][3],
                           bfrag[nt][0], bfrag[nt][1]);
        }
    };

    const int nK = 256 / 32;
    load_tile(0, 0);
    for (int it = 0; it < nK; ++it) {
        cp_wait0();
        __syncthreads();
        if (it + 1 < nK) load_tile((it+1) & 1, (it+1) * 32);
        compute(it & 1);
    }

#pragma unroll
    for (int mt = 0; mt < 2; mt++) {
        const int r0 = m0 + wm*32 + mt*16 + g;
        const int r1 = r0 + 8;
#pragma unroll
        for (int nt = 0; nt < 8; nt++) {
            const int c = n0 + wn*64 + nt*8 + tig*2;
            const float b0 = Bias[c], b1 = Bias[c+1];
            *(__half2*)(C + (size_t)r0*N + c) =
                __floats2half2_rn(acc[mt][nt][0] + b0, acc[mt][nt][1] + b1);
            *(__half2*)(C + (size_t)r1*N + c) =
                __floats2half2_rn(acc[mt][nt][2] + b0, acc[mt][nt][3] + b1);
        }
    }
}

// ------------- offsets + softmax + postprocess: one THREAD per query ---------
// Writes final (gx, gy, w) x 4 per query to samp.
__global__ void __launch_bounds__(256)
offw3_kernel(const float* __restrict__ q,
             const float* __restrict__ Wo, const float* __restrict__ bo,
             const float* __restrict__ Ww, const float* __restrict__ bw,
             const float* __restrict__ ref, float* __restrict__ samp)
{
    __shared__ float wcat[256*12];       // [k][12]: Wo row then Ww row
    __shared__ float qs[128*33];         // [row][k%32], pad 33 -> conflict-free

    const int t  = threadIdx.x;
    const int q0 = blockIdx.x * 128;

    {   // stage weights: thread t handles k-row t
        float4 w0 = *(const float4*)(Wo + t*8);
        float4 w1 = *(const float4*)(Wo + t*8 + 4);
        float4 w2 = *(const float4*)(Ww + t*4);
        *(float4*)&wcat[t*12 + 0] = w0;
        *(float4*)&wcat[t*12 + 4] = w1;
        *(float4*)&wcat[t*12 + 8] = w2;
    }

    float acc[12];
#pragma unroll
    for (int j = 0; j < 12; j++) acc[j] = 0.f;

    for (int k0 = 0; k0 < 256; k0 += 32) {
        __syncthreads();
#pragma unroll
        for (int i = 0; i < 4; i++) {
            const int idx4 = i*256 + t;          // 0..1023 float4s
            const int row  = idx4 >> 3;          // 0..127
            const int c4   = (idx4 & 7) * 4;     // 0..28
            float4 v = *(const float4*)(q + (size_t)(q0+row)*256 + k0 + c4);
            qs[row*33 + c4 + 0] = v.x; qs[row*33 + c4 + 1] = v.y;
            qs[row*33 + c4 + 2] = v.z; qs[row*33 + c4 + 3] = v.w;
        }
        __syncthreads();
        if (t < 128) {
#pragma unroll
            for (int kk = 0; kk < 32; kk++) {
                const float qv = qs[t*33 + kk];
                const float4 w0 = *(const float4*)&wcat[(k0+kk)*12 + 0];
                const float4 w1 = *(const float4*)&wcat[(k0+kk)*12 + 4];
                const float4 w2 = *(const float4*)&wcat[(k0+kk)*12 + 8];
                acc[0] = fmaf(qv, w0.x, acc[0]); acc[1] = fmaf(qv, w0.y, acc[1]);
                acc[2] = fmaf(qv, w0.z, acc[2]); acc[3] = fmaf(qv, w0.w, acc[3]);
                acc[4] = fmaf(qv, w1.x, acc[4]); acc[5] = fmaf(qv, w1.y, acc[5]);
                acc[6] = fmaf(qv, w1.z, acc[6]); acc[7] = fmaf(qv, w1.w, acc[7]);
                acc[8] = fmaf(qv, w2.x, acc[8]); acc[9] = fmaf(qv, w2.y, acc[9]);
                acc[10]= fmaf(qv, w2.z, acc[10]);acc[11]= fmaf(qv, w2.w, acc[11]);
            }
        }
    }

    if (t < 128) {
        const int qi = q0 + t;
        const float rx = ref[(size_t)qi*2+0];
        const float ry = ref[(size_t)qi*2+1];
        float v[4], mx = -1e30f;
#pragma unroll
        for (int j=0;j<4;j++) { v[j] = acc[8+j] + bw[j]; mx = fmaxf(mx, v[j]); }
        float s = 0.f;
#pragma unroll
        for (int j=0;j<4;j++) { v[j] = __expf(v[j]-mx); s += v[j]; }
        const float inv = 1.f / s;
        float o[12];
#pragma unroll
        for (int sI=0; sI<4; sI++) {
            float ox = tanhf(acc[2*sI+0] + bo[2*sI+0]) * OFFSET_SCALE;
            float oy = tanhf(acc[2*sI+1] + bo[2*sI+1]) * OFFSET_SCALE;
            o[sI*3+0] = fminf(fmaxf(rx + ox, -1.2f), 1.2f);
            o[sI*3+1] = fminf(fmaxf(ry + oy, -1.2f), 1.2f);
            o[sI*3+2] = v[sI]*inv;
        }
        float4* dst = (float4*)(samp + (size_t)qi*12);
        dst[0] = make_float4(o[0], o[1], o[2],  o[3]);
        dst[1] = make_float4(o[4], o[5], o[6],  o[7]);
        dst[2] = make_float4(o[8], o[9], o[10], o[11]);
    }
}

// ------------- gather-only bilinear sampler: one warp per query --------------
#define QPW 4
__global__ void __launch_bounds__(256)
sample4_kernel(const __half* __restrict__ pf, const float* __restrict__ samp,
               const int* __restrict__ mask, __half* __restrict__ ctx)
{
    const int t = threadIdx.x;
    const int wid = t >> 5, lane = t & 31;
    const int d = lane * 8;              // 8 fp16 channels per lane

    for (int itq = 0; itq < QPW; itq++) {
        const int qi = (blockIdx.x * 8 + wid) * QPW + itq;

        if (!mask[qi]) {
            uint4 z = make_uint4(0,0,0,0);
            *(uint4*)(ctx + (size_t)qi*256 + d) = z;
            continue;
        }

        // uniform (broadcast) load of precomputed sample params
        const float4* spp = (const float4*)(samp + (size_t)qi*12);
        const float4 s0 = spp[0], s1 = spp[1], s2 = spp[2];
        const float sp[12] = { s0.x, s0.y, s0.z, s0.w,
                               s1.x, s1.y, s1.z, s1.w,
                               s2.x, s2.y, s2.z, s2.w };

        const __half* base = pf + ((((size_t)(qi >> 14)) << 14)) * 256;
        float a8[8] = {0.f,0.f,0.f,0.f,0.f,0.f,0.f,0.f};
#pragma unroll
        for (int s = 0; s < 4; s++) {
            const float gx = sp[s*3+0], gy = sp[s*3+1], w = sp[s*3+2];
            const float x = (gx + 1.f) * 0.5f * (WW - 1);
            const float y = (gy + 1.f) * 0.5f * (HH - 1);
            const float x0f = floorf(x), y0f = floorf(y);
            const int x0 = (int)x0f, y0 = (int)y0f;
            const float wx1 = x - x0f, wy1 = y - y0f;
            const float wx0 = 1.f - wx1, wy0 = 1.f - wy1;
            const int   xs[2]  = {x0, x0+1};
            const int   ys[2]  = {y0, y0+1};
            const float wxs[2] = {wx0, wx1};
            const float wys[2] = {wy0, wy1};
#pragma unroll
            for (int cy=0; cy<2; cy++)
#pragma unroll
                for (int cx=0; cx<2; cx++) {
                    const int xi = xs[cx], yi = ys[cy];
                    if (xi >= 0 && xi < WW && yi >= 0 && yi < HH) {
                        const float cw = w * wxs[cx] * wys[cy];
                        const uint4 vv = *(const uint4*)(base + ((size_t)(yi*WW + xi))*256 + d);
                        const __half2* h = (const __half2*)&vv;
#pragma unroll
                        for (int p = 0; p < 4; p++) {
                            float2 f = __half22float2(h[p]);
                            a8[2*p+0] = fmaf(cw, f.x, a8[2*p+0]);
                            a8[2*p+1] = fmaf(cw, f.y, a8[2*p+1]);
                        }
                    }
                }
        }

        __half2 o0 = __floats2half2_rn(a8[0], a8[1]);
        __half2 o1 = __floats2half2_rn(a8[2], a8[3]);
        __half2 o2 = __floats2half2_rn(a8[4], a8[5]);
        __half2 o3 = __floats2half2_rn(a8[6], a8[7]);
        uint4 o;
        o.x = *(unsigned*)&o0; o.y = *(unsigned*)&o1;
        o.z = *(unsigned*)&o2; o.w = *(unsigned*)&o3;
        *(uint4*)(ctx + (size_t)qi*256 + d) = o;
    }
}

// -----------------------------------------------------------------------------
extern "C" void kernel_launch(void* const* d_in, const int* in_sizes, int n_in,
                              void* d_out, int out_size)
{
    const float* queries  = (const float*)d_in[0];
    const float* ref_pts  = (const float*)d_in[1];
    const float* fmap     = (const float*)d_in[2];
    const int*   vmask    = (const int*)  d_in[3];
    const float* Wq = (const float*)d_in[4];
    const float* bq = (const float*)d_in[5];
    const float* Wf = (const float*)d_in[6];
    const float* bf = (const float*)d_in[7];
    const float* Wo = (const float*)d_in[8];
    const float* bo = (const float*)d_in[9];
    const float* Ww = (const float*)d_in[10];
    const float* bw = (const float*)d_in[11];
    const float* W1 = (const float*)d_in[12];
    const float* b1 = (const float*)d_in[13];
    const float* W2 = (const float*)d_in[14];
    const float* b2 = (const float*)d_in[15];
    float* out = (float*)d_out;

    __half *pfh, *pqh, *ctxh, *h1h, *Wqh, *Wfh, *W1h, *W2h;
    float *samp;
    cudaGetSymbolAddress((void**)&pfh,  g_pf);
    cudaGetSymbolAddress((void**)&pqh,  g_pq);
    cudaGetSymbolAddress((void**)&ctxh, g_ctx);
    cudaGetSymbolAddress((void**)&h1h,  g_h1);
    cudaGetSymbolAddress((void**)&samp, g_samp);
    cudaGetSymbolAddress((void**)&Wqh,  g_Wqh);
    cudaGetSymbolAddress((void**)&Wfh,  g_Wfh);
    cudaGetSymbolAddress((void**)&W1h,  g_W1h);
    cudaGetSymbolAddress((void**)&W2h,  g_W2h);

    const dim3 gGemm(256/128, MTOT/128);    // (2, 512)

    // 0) weights fp32 -> fp16
    convw_kernel<<<320, 256>>>(Wq, Wf, W1, W2, Wqh, Wfh, W1h, W2h);
    // 1) pf = conv1x1(fmap CHW, Wf) + bf   -> fp16 HWC
    gemm_pf<<<gGemm, 256>>>(fmap, Wfh, bf, pfh, 256);
    // 2) pq = (queries @ Wq + bq) * mask   -> fp16
    gemm_a<0, float, __half><<<gGemm, 256>>>(queries, nullptr, Wqh, bq, pqh,
                                             MTOT, 256, 256, 0, vmask);
    // 3) offsets + softmax + postprocess -> samp
    offw3_kernel<<<MTOT/128, 256>>>(queries, Wo, bo, Ww, bw, ref_pts, samp);
    // 4) gather-only bilinear sample -> ctx fp16 (masked)
    sample4_kernel<<<MTOT/(8*QPW), 256>>>(pfh, samp, vmask, ctxh);
    // 5) h1 = relu([pq|ctx] @ W1 + b1)     -> fp16
    gemm_a<2, __half, __half><<<gGemm, 256>>>(pqh, ctxh, W1h, b1, h1h,
                                              MTOT, 256, 512, 1, nullptr);
    // 6) out = h1 @ W2 + b2                -> fp32
    gemm_a<0, __half, float><<<gGemm, 256>>>(h1h, nullptr, W2h, b2, out,
                                             MTOT, 256, 256, 0, nullptr);
}